// round 6
// baseline (speedup 1.0000x reference)
#include <cuda_runtime.h>
#include <cuda_bf16.h>
#include <cstdint>

#define N_NODES  50000
#define N_EDGES  800000
#define HID      128
#define EDGE_D   16
#define N_GRAPHS 64

#define ETILE 128
#define NTILE 32
#define NUM_ETILES (N_EDGES / ETILE)
#define ETHREADS 1024

// ---------------- device scratch (static, no allocation) ----------------
__device__ float g_hAB[(size_t)N_NODES * 256];   // hA | hB  (51.2 MB)
__device__ float g_agg[(size_t)N_NODES * HID];   // scatter target (25.6 MB)
__device__ float g_Wcat[128 * 256];              // [We1a | We1b] rearranged
__device__ float g_pool[N_GRAPHS * HID];
__device__ float g_cnt[N_GRAPHS];
__device__ int   g_row[N_EDGES];
__device__ int   g_col[N_EDGES];
__device__ int   g_batch[N_NODES];
__device__ int   g_is64;

__device__ __forceinline__ float silu_f(float v) {
    return __fdividef(v, 1.0f + __expf(-v));
}

// bf16 mma m16n8k16: D += A(16x16) * B(16x8), A row-major, B col-major
__device__ __forceinline__ void mma_bf16(float* d, uint32_t a0, uint32_t a1,
                                         uint32_t a2, uint32_t a3,
                                         uint32_t b0, uint32_t b1) {
    asm volatile(
        "mma.sync.aligned.m16n8k16.row.col.f32.bf16.bf16.f32 "
        "{%0,%1,%2,%3}, {%4,%5,%6,%7}, {%8,%9}, {%0,%1,%2,%3};"
        : "+f"(d[0]), "+f"(d[1]), "+f"(d[2]), "+f"(d[3])
        : "r"(a0), "r"(a1), "r"(a2), "r"(a3), "r"(b0), "r"(b1));
}

// ---------------- small prep kernels ----------------
__global__ void k_detect(const void* __restrict__ ei) {
    const unsigned int* p = (const unsigned int*)ei;
    int is64 = 1;
    for (int i = 0; i < 16; i++) if (p[2 * i + 1] != 0u) is64 = 0;
    g_is64 = is64;
}

__global__ void k_cvt_idx(const void* __restrict__ ei, const void* __restrict__ batch) {
    const int i = blockIdx.x * blockDim.x + threadIdx.x;
    const bool is64 = (g_is64 != 0);
    if (i < N_EDGES) {
        if (is64) {
            const long long* p = (const long long*)ei;
            g_row[i] = (int)p[i];
            g_col[i] = (int)p[N_EDGES + i];
        } else {
            const int* p = (const int*)ei;
            g_row[i] = p[i];
            g_col[i] = p[N_EDGES + i];
        }
    }
    if (i < N_NODES) {
        if (is64) g_batch[i] = (int)((const long long*)batch)[i];
        else      g_batch[i] = ((const int*)batch)[i];
    }
}

__global__ void k_zero_agg() {
    const int i = blockIdx.x * blockDim.x + threadIdx.x;
    if (i < (N_NODES * HID) / 4)
        reinterpret_cast<float4*>(g_agg)[i] = make_float4(0.f, 0.f, 0.f, 0.f);
}

__global__ void k_zero_pool() {
    const int i = blockIdx.x * blockDim.x + threadIdx.x;
    if (i < N_GRAPHS * HID) g_pool[i] = 0.f;
    if (i < N_GRAPHS)       g_cnt[i] = 0.f;
}

__global__ void k_prep_wcat(const float* __restrict__ We1) {
    const int i = blockIdx.x * blockDim.x + threadIdx.x;
    if (i < 128 * 256) {
        const int k = i >> 8, c = i & 255;
        g_Wcat[i] = (c < 128) ? We1[k * 128 + c] : We1[(128 + k) * 128 + (c - 128)];
    }
}

// ---------------- node pre-GEMM: g_hAB[n] = h[n] @ [We1a|We1b] (+be1 on cols<128)
__global__ __launch_bounds__(256) void k_node_pre(const float* __restrict__ h,
                                                  const float* __restrict__ be1) {
    __shared__ float a_s[128 * 36];
    const int n0 = blockIdx.x * NTILE;
    const int t = threadIdx.x;
    {
        const int n  = t >> 3;
        const int k4 = t & 7;
        const int ng = n0 + n;
#pragma unroll
        for (int j = 0; j < 4; j++) {
            const int k = k4 * 16 + j * 4;
            float4 v = make_float4(0.f, 0.f, 0.f, 0.f);
            if (ng < N_NODES) v = *reinterpret_cast<const float4*>(h + (size_t)ng * 128 + k);
            a_s[(k + 0) * 36 + n] = v.x;
            a_s[(k + 1) * 36 + n] = v.y;
            a_s[(k + 2) * 36 + n] = v.z;
            a_s[(k + 3) * 36 + n] = v.w;
        }
    }
    __syncthreads();
    const int cg = t & 31;
    const int ng = t >> 5;
    float acc[4][8];
#pragma unroll
    for (int i = 0; i < 4; i++)
#pragma unroll
        for (int j = 0; j < 8; j++) acc[i][j] = 0.f;

    const float* wbase = g_Wcat + cg * 8;
    for (int k = 0; k < 128; k++) {
        const float4 a  = *reinterpret_cast<const float4*>(&a_s[k * 36 + ng * 4]);
        const float4 w0 = __ldg(reinterpret_cast<const float4*>(wbase + k * 256));
        const float4 w1 = __ldg(reinterpret_cast<const float4*>(wbase + k * 256 + 4));
        const float av[4] = {a.x, a.y, a.z, a.w};
        const float wv[8] = {w0.x, w0.y, w0.z, w0.w, w1.x, w1.y, w1.z, w1.w};
#pragma unroll
        for (int i = 0; i < 4; i++)
#pragma unroll
            for (int j = 0; j < 8; j++) acc[i][j] = fmaf(av[i], wv[j], acc[i][j]);
    }
    const int cbase = cg * 8;
    float bias[8];
#pragma unroll
    for (int j = 0; j < 8; j++) bias[j] = (cbase + j < 128) ? __ldg(be1 + cbase + j) : 0.f;
#pragma unroll
    for (int i = 0; i < 4; i++) {
        const int n = n0 + ng * 4 + i;
        if (n < N_NODES) {
            float4 o0 = make_float4(acc[i][0] + bias[0], acc[i][1] + bias[1],
                                    acc[i][2] + bias[2], acc[i][3] + bias[3]);
            float4 o1 = make_float4(acc[i][4] + bias[4], acc[i][5] + bias[5],
                                    acc[i][6] + bias[6], acc[i][7] + bias[7]);
            *reinterpret_cast<float4*>(g_hAB + (size_t)n * 256 + cbase)     = o0;
            *reinterpret_cast<float4*>(g_hAB + (size_t)n * 256 + cbase + 4) = o1;
        }
    }
}

// ---------------- fused edge kernel (persistent, 1024 thr, bf16 mma.sync 3-term GEMM2) ----
#define SB_W2H   0                 // 128x136 bf16 = 34816 B  (W2^T hi, [c][k])
#define SB_W2L   34816             // 34816 B                 (W2^T lo)
#define SB_UHI   69632             // 34816 B                 (u hi, [e][k])
#define SB_ULO   104448            // 34816 B                 (u lo)
#define SB_W1E   139264            // 2048 f32 = 8192 B
#define SB_W1R   147456            // 128 f32
#define SB_BE2   147968            // 128 f32
#define SB_RAD   148480            // 128 f32
#define SB_ROW   148992            // 128 int
#define SB_COL   149504            // 128 int
#define SB_EA    150016            // 2048 f32 = 8192 B
#define EDGE_SMEM_BYTES 158208

#define BSTRIDE 136   // bf16 elements per row (272 B) -> banks 4g+tq, conflict-free

__global__ __launch_bounds__(ETHREADS, 1) void k_edge(const float* __restrict__ x,
                                                      const float* __restrict__ ea,
                                                      const float* __restrict__ We1,
                                                      const float* __restrict__ We2,
                                                      const float* __restrict__ be2) {
    extern __shared__ char smem[];
    __nv_bfloat16* w2h = reinterpret_cast<__nv_bfloat16*>(smem + SB_W2H);
    __nv_bfloat16* w2l = reinterpret_cast<__nv_bfloat16*>(smem + SB_W2L);
    __nv_bfloat16* uhi = reinterpret_cast<__nv_bfloat16*>(smem + SB_UHI);
    __nv_bfloat16* ulo = reinterpret_cast<__nv_bfloat16*>(smem + SB_ULO);
    float* W1e_s = reinterpret_cast<float*>(smem + SB_W1E);
    float* W1r_s = reinterpret_cast<float*>(smem + SB_W1R);
    float* be2_s = reinterpret_cast<float*>(smem + SB_BE2);
    float* rad_s = reinterpret_cast<float*>(smem + SB_RAD);
    int*   row_s = reinterpret_cast<int*>(smem + SB_ROW);
    int*   col_s = reinterpret_cast<int*>(smem + SB_COL);
    float* ea_s  = reinterpret_cast<float*>(smem + SB_EA);

    const int t = threadIdx.x;
    const int w = t >> 5, lane = t & 31;

    // stage W2^T hi/lo (once per persistent block): We2 is [k][c] -> w2*[c][k]
    for (int i = t; i < 16384; i += ETHREADS) {
        const int k = i >> 7, c = i & 127;
        const float v = We2[i];
        const __nv_bfloat16 hi = __float2bfloat16(v);
        w2h[c * BSTRIDE + k] = hi;
        w2l[c * BSTRIDE + k] = __float2bfloat16(v - __bfloat162float(hi));
    }
    for (int i = t; i < 2048; i += ETHREADS) W1e_s[i] = We1[257 * 128 + i];
    if (t < 128) {
        W1r_s[t] = We1[256 * 128 + t];
        be2_s[t] = be2[t];
    }

    // Phase-B warp tiling: 32 warps -> m16 (mt=w&7) x n32 (nq=w>>3)
    const int mt = w & 7;
    const int nq = w >> 3;       // 0..3
    const int g  = lane >> 2;    // 0..7
    const int tq = lane & 3;     // 0..3

    for (int tile = blockIdx.x; tile < NUM_ETILES; tile += gridDim.x) {
        const int e0 = tile * ETILE;
        __syncthreads();   // guard smem tile buffers vs previous iteration readers

        for (int i = t; i < 2048; i += ETHREADS) ea_s[i] = ea[(size_t)e0 * 16 + i];
        if (t < 128) {
            const int eg = e0 + t;
            const int r = g_row[eg];
            const int c = g_col[eg];
            row_s[t] = r;
            col_s[t] = c;
            const float dx = x[r * 3 + 0] - x[c * 3 + 0];
            const float dy = x[r * 3 + 1] - x[c * 3 + 1];
            const float dz = x[r * 3 + 2] - x[c * 3 + 2];
            rad_s[t] = dx * dx + dy * dy + dz * dz;
        }
        __syncthreads();

        // ---- Phase A: u = silu(hA[row]+hB[col]+rad*W1r+ea@W1e); split hi/lo bf16 -> smem
        {
            const int ebase = w * 4;       // 32 warps x 4 edges
            const int co    = lane * 4;
            const float4 wr = *reinterpret_cast<const float4*>(W1r_s + co);
#pragma unroll
            for (int ii = 0; ii < 4; ii++) {
                const int e = ebase + ii;
                const float4 a4 = *reinterpret_cast<const float4*>(g_hAB + (size_t)row_s[e] * 256 + co);
                const float4 b4 = *reinterpret_cast<const float4*>(g_hAB + (size_t)col_s[e] * 256 + 128 + co);
                const float rad = rad_s[e];
                float tx = fmaf(rad, wr.x, a4.x + b4.x);
                float ty = fmaf(rad, wr.y, a4.y + b4.y);
                float tz = fmaf(rad, wr.z, a4.z + b4.z);
                float tw = fmaf(rad, wr.w, a4.w + b4.w);
#pragma unroll
                for (int j = 0; j < 16; j++) {
                    const float ej = ea_s[e * 16 + j];
                    const float4 wv = *reinterpret_cast<const float4*>(W1e_s + j * 128 + co);
                    tx = fmaf(ej, wv.x, tx);
                    ty = fmaf(ej, wv.y, ty);
                    tz = fmaf(ej, wv.z, tz);
                    tw = fmaf(ej, wv.w, tw);
                }
                const float sx = silu_f(tx), sy = silu_f(ty);
                const float sz = silu_f(tz), sw = silu_f(tw);
                const __nv_bfloat16 hx = __float2bfloat16(sx);
                const __nv_bfloat16 hy = __float2bfloat16(sy);
                const __nv_bfloat16 hz = __float2bfloat16(sz);
                const __nv_bfloat16 hw = __float2bfloat16(sw);
                __nv_bfloat162 hp0; hp0.x = hx; hp0.y = hy;
                __nv_bfloat162 hp1; hp1.x = hz; hp1.y = hw;
                uint2 hv;
                hv.x = *reinterpret_cast<uint32_t*>(&hp0);
                hv.y = *reinterpret_cast<uint32_t*>(&hp1);
                *reinterpret_cast<uint2*>(uhi + e * BSTRIDE + co) = hv;
                __nv_bfloat162 lp0;
                lp0.x = __float2bfloat16(sx - __bfloat162float(hx));
                lp0.y = __float2bfloat16(sy - __bfloat162float(hy));
                __nv_bfloat162 lp1;
                lp1.x = __float2bfloat16(sz - __bfloat162float(hz));
                lp1.y = __float2bfloat16(sw - __bfloat162float(hw));
                uint2 lv;
                lv.x = *reinterpret_cast<uint32_t*>(&lp0);
                lv.y = *reinterpret_cast<uint32_t*>(&lp1);
                *reinterpret_cast<uint2*>(ulo + e * BSTRIDE + co) = lv;
            }
        }
        __syncthreads();

        // ---- Phase B: D = u_hi@W_hi + u_lo@W_hi + u_hi@W_lo via bf16 mma.sync
        {
            float d[4][4];
#pragma unroll
            for (int nt = 0; nt < 4; nt++)
#pragma unroll
                for (int j = 0; j < 4; j++) d[nt][j] = 0.f;

#pragma unroll
            for (int term = 0; term < 3; term++) {
                const __nv_bfloat16* A = (term == 1) ? ulo : uhi;
                const __nv_bfloat16* B = (term == 2) ? w2l : w2h;
                const __nv_bfloat16* Ar0 = A + (mt * 16 + g) * BSTRIDE + 2 * tq;
                const __nv_bfloat16* Ar1 = Ar0 + 8 * BSTRIDE;
                const __nv_bfloat16* Bb  = B + (nq * 32 + g) * BSTRIDE + 2 * tq;
#pragma unroll
                for (int ks = 0; ks < 8; ks++) {
                    const int kb = ks * 16;
                    const uint32_t a0 = *reinterpret_cast<const uint32_t*>(Ar0 + kb);
                    const uint32_t a1 = *reinterpret_cast<const uint32_t*>(Ar1 + kb);
                    const uint32_t a2 = *reinterpret_cast<const uint32_t*>(Ar0 + kb + 8);
                    const uint32_t a3 = *reinterpret_cast<const uint32_t*>(Ar1 + kb + 8);
#pragma unroll
                    for (int nt = 0; nt < 4; nt++) {
                        const __nv_bfloat16* Bp = Bb + nt * 8 * BSTRIDE + kb;
                        const uint32_t b0 = *reinterpret_cast<const uint32_t*>(Bp);
                        const uint32_t b1 = *reinterpret_cast<const uint32_t*>(Bp + 8);
                        mma_bf16(d[nt], a0, a1, a2, a3, b0, b1);
                    }
                }
            }

            // epilogue: silu(+bias) then red.v2 scatter (cols come in aligned even pairs)
            const int er0 = row_s[mt * 16 + g];
            const int er1 = row_s[mt * 16 + g + 8];
#pragma unroll
            for (int nt = 0; nt < 4; nt++) {
                const int col = nq * 32 + nt * 8 + 2 * tq;
                const float b0v = be2_s[col];
                const float b1v = be2_s[col + 1];
                const float v00 = silu_f(d[nt][0] + b0v);
                const float v01 = silu_f(d[nt][1] + b1v);
                const float v10 = silu_f(d[nt][2] + b0v);
                const float v11 = silu_f(d[nt][3] + b1v);
                asm volatile("red.global.add.v2.f32 [%0], {%1, %2};"
                             :: "l"(g_agg + (size_t)er0 * 128 + col), "f"(v00), "f"(v01) : "memory");
                asm volatile("red.global.add.v2.f32 [%0], {%1, %2};"
                             :: "l"(g_agg + (size_t)er1 * 128 + col), "f"(v10), "f"(v11) : "memory");
            }
        }
    }
}

// ---------------- node MLP + residual + pooled scatter ----------------
#define NODE_SMEM_FLOATS (256 * 36 + 128 * 33 + 32)
#define NODE_SMEM_BYTES  (NODE_SMEM_FLOATS * 4)

__global__ __launch_bounds__(256) void k_node(const float* __restrict__ h,
                                              const float* __restrict__ Wn1,
                                              const float* __restrict__ bn1,
                                              const float* __restrict__ Wn2,
                                              const float* __restrict__ bn2) {
    extern __shared__ float sm[];
    float* a_s = sm;
    float* m_s = sm + 256 * 36;
    int*   b_s = reinterpret_cast<int*>(sm + 256 * 36 + 128 * 33);

    const int n0 = blockIdx.x * NTILE;
    const int t = threadIdx.x;
    {
        const int n  = t >> 3;
        const int k4 = t & 7;
        const int ng = n0 + n;
#pragma unroll
        for (int j = 0; j < 4; j++) {
            const int k = k4 * 16 + j * 4;
            float4 v = make_float4(0.f, 0.f, 0.f, 0.f);
            float4 w = make_float4(0.f, 0.f, 0.f, 0.f);
            if (ng < N_NODES) {
                v = *reinterpret_cast<const float4*>(h + (size_t)ng * 128 + k);
                w = *reinterpret_cast<const float4*>(g_agg + (size_t)ng * 128 + k);
            }
            a_s[(k + 0) * 36 + n] = v.x;
            a_s[(k + 1) * 36 + n] = v.y;
            a_s[(k + 2) * 36 + n] = v.z;
            a_s[(k + 3) * 36 + n] = v.w;
            a_s[(128 + k + 0) * 36 + n] = w.x;
            a_s[(128 + k + 1) * 36 + n] = w.y;
            a_s[(128 + k + 2) * 36 + n] = w.z;
            a_s[(128 + k + 3) * 36 + n] = w.w;
        }
        if (t < 32) b_s[t] = (n0 + t < N_NODES) ? g_batch[n0 + t] : 0;
    }
    __syncthreads();

    const int cg = t & 31;
    const int ng = t >> 5;
    float acc[4][4];
#pragma unroll
    for (int i = 0; i < 4; i++)
#pragma unroll
        for (int j = 0; j < 4; j++) acc[i][j] = 0.f;

    for (int k = 0; k < 256; k++) {
        float av[4];
#pragma unroll
        for (int i = 0; i < 4; i++) av[i] = a_s[k * 36 + ng * 4 + i];
        const float4 w = __ldg(reinterpret_cast<const float4*>(Wn1 + k * 128 + cg * 4));
        const float wv[4] = {w.x, w.y, w.z, w.w};
#pragma unroll
        for (int i = 0; i < 4; i++)
#pragma unroll
            for (int j = 0; j < 4; j++) acc[i][j] = fmaf(av[i], wv[j], acc[i][j]);
    }
#pragma unroll
    for (int j = 0; j < 4; j++) {
        const int c = cg * 4 + j;
        const float b = __ldg(bn1 + c);
#pragma unroll
        for (int i = 0; i < 4; i++)
            m_s[c * 33 + ng * 4 + i] = silu_f(acc[i][j] + b);
    }
    __syncthreads();

    float acc2[4][4];
#pragma unroll
    for (int i = 0; i < 4; i++)
#pragma unroll
        for (int j = 0; j < 4; j++) acc2[i][j] = 0.f;

    for (int k = 0; k < 128; k++) {
        float av[4];
#pragma unroll
        for (int i = 0; i < 4; i++) av[i] = m_s[k * 33 + ng * 4 + i];
        const float4 w = __ldg(reinterpret_cast<const float4*>(Wn2 + k * 128 + cg * 4));
        const float wv[4] = {w.x, w.y, w.z, w.w};
#pragma unroll
        for (int i = 0; i < 4; i++)
#pragma unroll
            for (int j = 0; j < 4; j++) acc2[i][j] = fmaf(av[i], wv[j], acc2[i][j]);
    }
#pragma unroll
    for (int i = 0; i < 4; i++) {
        const int n = n0 + ng * 4 + i;
        if (n < N_NODES) {
            const int b = b_s[ng * 4 + i];
#pragma unroll
            for (int j = 0; j < 4; j++) {
                const int c = cg * 4 + j;
                const float hn = acc2[i][j] + __ldg(bn2 + c) + a_s[c * 36 + ng * 4 + i];
                atomicAdd(&g_pool[b * 128 + c], hn);
            }
        }
    }
    if (t < 32 && n0 + t < N_NODES) atomicAdd(&g_cnt[b_s[t]], 1.0f);
}

__global__ void k_pool_final(float* __restrict__ out) {
    const int g = blockIdx.x;
    const int c = threadIdx.x;
    const float cnt = fmaxf(g_cnt[g], 1.0f);
    out[g * 128 + c] = g_pool[g * 128 + c] / cnt;
}

// ---------------- launcher ----------------
extern "C" void kernel_launch(void* const* d_in, const int* in_sizes, int n_in,
                              void* d_out, int out_size) {
    const float* h   = (const float*)d_in[0];
    const void*  ei  = d_in[1];
    const float* x   = (const float*)d_in[2];
    const float* ea  = (const float*)d_in[3];
    const void*  bat = d_in[4];
    const float* We1 = (const float*)d_in[5];
    const float* be1 = (const float*)d_in[6];
    const float* We2 = (const float*)d_in[7];
    const float* be2 = (const float*)d_in[8];
    const float* Wn1 = (const float*)d_in[9];
    const float* bn1 = (const float*)d_in[10];
    const float* Wn2 = (const float*)d_in[11];
    const float* bn2 = (const float*)d_in[12];
    float* out = (float*)d_out;

    cudaFuncSetAttribute(k_edge, cudaFuncAttributeMaxDynamicSharedMemorySize, EDGE_SMEM_BYTES);
    cudaFuncSetAttribute(k_node, cudaFuncAttributeMaxDynamicSharedMemorySize, NODE_SMEM_BYTES);

    k_detect<<<1, 1>>>(ei);
    k_cvt_idx<<<(N_EDGES + 255) / 256, 256>>>(ei, bat);
    k_zero_agg<<<(N_NODES * HID / 4 + 255) / 256, 256>>>();
    k_zero_pool<<<(N_GRAPHS * HID + 255) / 256, 256>>>();
    k_prep_wcat<<<(128 * 256 + 255) / 256, 256>>>(We1);
    k_node_pre<<<(N_NODES + NTILE - 1) / NTILE, 256>>>(h, be1);
    k_edge<<<152, ETHREADS, EDGE_SMEM_BYTES>>>(x, ea, We1, We2, be2);
    k_node<<<(N_NODES + NTILE - 1) / NTILE, 256, NODE_SMEM_BYTES>>>(h, Wn1, bn1, Wn2, bn2);
    k_pool_final<<<N_GRAPHS, HID>>>(out);
}

// round 7
// speedup vs baseline: 1.2411x; 1.2411x over previous
#include <cuda_runtime.h>
#include <cuda_bf16.h>
#include <cstdint>

#define N_NODES  50000
#define N_EDGES  800000
#define HID      128
#define EDGE_D   16
#define N_GRAPHS 64

#define ETILE 128
#define NTILE 32
#define NUM_ETILES (N_EDGES / ETILE)

// ---------------- device scratch (static, no allocation) ----------------
__device__ float g_hAB[(size_t)N_NODES * 256];   // hA | hB  (51.2 MB)
__device__ float g_agg[(size_t)N_NODES * HID];   // scatter target (25.6 MB)
__device__ float g_pool[N_GRAPHS * HID];
__device__ float g_cnt[N_GRAPHS];
__device__ int   g_row[N_EDGES];
__device__ int   g_col[N_EDGES];
__device__ int   g_batch[N_NODES];
__device__ int   g_is64;

__device__ __forceinline__ float silu_f(float v) {
    return __fdividef(v, 1.0f + __expf(-v));
}

// bf16 mma m16n8k16: D += A(16x16) * B(16x8), A row-major, B col-major
__device__ __forceinline__ void mma_bf16(float* d, uint32_t a0, uint32_t a1,
                                         uint32_t a2, uint32_t a3,
                                         uint32_t b0, uint32_t b1) {
    asm volatile(
        "mma.sync.aligned.m16n8k16.row.col.f32.bf16.bf16.f32 "
        "{%0,%1,%2,%3}, {%4,%5,%6,%7}, {%8,%9}, {%0,%1,%2,%3};"
        : "+f"(d[0]), "+f"(d[1]), "+f"(d[2]), "+f"(d[3])
        : "r"(a0), "r"(a1), "r"(a2), "r"(a3), "r"(b0), "r"(b1));
}

// ---------------- init: zero agg+pool, detect index width (launch #1) ----------------
__global__ void k_init(const void* __restrict__ ei) {
    const int i = blockIdx.x * blockDim.x + threadIdx.x;
    if (i < (N_NODES * HID) / 4)
        reinterpret_cast<float4*>(g_agg)[i] = make_float4(0.f, 0.f, 0.f, 0.f);
    if (i < N_GRAPHS * HID) g_pool[i] = 0.f;
    if (i < N_GRAPHS)       g_cnt[i] = 0.f;
    if (i == 0) {
        const unsigned int* p = (const unsigned int*)ei;
        int is64 = 1;
        for (int j = 0; j < 16; j++) if (p[2 * j + 1] != 0u) is64 = 0;
        g_is64 = is64;
    }
}

// ---------------- index conversion (launch #2) ----------------
__global__ void k_cvt_idx(const void* __restrict__ ei, const void* __restrict__ batch) {
    const int i = blockIdx.x * blockDim.x + threadIdx.x;
    const bool is64 = (g_is64 != 0);
    if (i < N_EDGES) {
        if (is64) {
            const long long* p = (const long long*)ei;
            g_row[i] = (int)p[i];
            g_col[i] = (int)p[N_EDGES + i];
        } else {
            const int* p = (const int*)ei;
            g_row[i] = p[i];
            g_col[i] = p[N_EDGES + i];
        }
    }
    if (i < N_NODES) {
        if (is64) g_batch[i] = (int)((const long long*)batch)[i];
        else      g_batch[i] = ((const int*)batch)[i];
    }
}

// ---------------- node pre-GEMM (launch #3): g_hAB[n] = h[n] @ [We1a|We1b] (+be1 on cols<128)
__global__ __launch_bounds__(256) void k_node_pre(const float* __restrict__ h,
                                                  const float* __restrict__ We1,
                                                  const float* __restrict__ be1) {
    __shared__ float a_s[128 * 36];
    const int n0 = blockIdx.x * NTILE;
    const int t = threadIdx.x;
    {
        const int n  = t >> 3;
        const int k4 = t & 7;
        const int ng = n0 + n;
#pragma unroll
        for (int j = 0; j < 4; j++) {
            const int k = k4 * 16 + j * 4;
            float4 v = make_float4(0.f, 0.f, 0.f, 0.f);
            if (ng < N_NODES) v = *reinterpret_cast<const float4*>(h + (size_t)ng * 128 + k);
            a_s[(k + 0) * 36 + n] = v.x;
            a_s[(k + 1) * 36 + n] = v.y;
            a_s[(k + 2) * 36 + n] = v.z;
            a_s[(k + 3) * 36 + n] = v.w;
        }
    }
    __syncthreads();
    const int cg = t & 31;                    // 32 groups x 8 cols = 256 concat cols
    const int ng = t >> 5;
    const int cbase = cg * 8;
    // direct We1 access: cols<128 -> We1[k*128+cbase]; cols>=128 -> We1[(128+k)*128 + cbase-128]
    const float* wptr = (cbase < 128) ? (We1 + cbase) : (We1 + 128 * 128 + (cbase - 128));
    float acc[4][8];
#pragma unroll
    for (int i = 0; i < 4; i++)
#pragma unroll
        for (int j = 0; j < 8; j++) acc[i][j] = 0.f;

    for (int k = 0; k < 128; k++) {
        const float4 a  = *reinterpret_cast<const float4*>(&a_s[k * 36 + ng * 4]);
        const float4 w0 = __ldg(reinterpret_cast<const float4*>(wptr + k * 128));
        const float4 w1 = __ldg(reinterpret_cast<const float4*>(wptr + k * 128 + 4));
        const float av[4] = {a.x, a.y, a.z, a.w};
        const float wv[8] = {w0.x, w0.y, w0.z, w0.w, w1.x, w1.y, w1.z, w1.w};
#pragma unroll
        for (int i = 0; i < 4; i++)
#pragma unroll
            for (int j = 0; j < 8; j++) acc[i][j] = fmaf(av[i], wv[j], acc[i][j]);
    }
    float bias[8];
#pragma unroll
    for (int j = 0; j < 8; j++) bias[j] = (cbase + j < 128) ? __ldg(be1 + cbase + j) : 0.f;
#pragma unroll
    for (int i = 0; i < 4; i++) {
        const int n = n0 + ng * 4 + i;
        if (n < N_NODES) {
            float4 o0 = make_float4(acc[i][0] + bias[0], acc[i][1] + bias[1],
                                    acc[i][2] + bias[2], acc[i][3] + bias[3]);
            float4 o1 = make_float4(acc[i][4] + bias[4], acc[i][5] + bias[5],
                                    acc[i][6] + bias[6], acc[i][7] + bias[7]);
            *reinterpret_cast<float4*>(g_hAB + (size_t)n * 256 + cbase)     = o0;
            *reinterpret_cast<float4*>(g_hAB + (size_t)n * 256 + cbase + 4) = o1;
        }
    }
}

// ---------------- fused edge kernel (launch #4; persistent, 512 thr, bf16 mma 3-term) ----
#define SB_W2H   0                 // 128x136 bf16 = 34816 B  (W2^T hi, [c][k])
#define SB_W2L   34816             // 34816 B                 (W2^T lo)
#define SB_UHI   69632             // 34816 B                 (u hi, [e][k])
#define SB_ULO   104448            // 34816 B                 (u lo)
#define SB_W1E   139264            // 2048 f32 = 8192 B
#define SB_W1R   147456            // 128 f32
#define SB_BE2   147968            // 128 f32
#define SB_RAD   148480            // 128 f32
#define SB_ROW   148992            // 128 int
#define SB_COL   149504            // 128 int
#define SB_EA    150016            // 2048 f32 = 8192 B
#define EDGE_SMEM_BYTES 158208

#define BSTRIDE 136   // bf16 elements per row (272 B) -> banks 4g+tq, conflict-free

__global__ __launch_bounds__(512, 1) void k_edge(const float* __restrict__ x,
                                                 const float* __restrict__ ea,
                                                 const float* __restrict__ We1,
                                                 const float* __restrict__ We2,
                                                 const float* __restrict__ be2) {
    extern __shared__ char smem[];
    __nv_bfloat16* w2h = reinterpret_cast<__nv_bfloat16*>(smem + SB_W2H);
    __nv_bfloat16* w2l = reinterpret_cast<__nv_bfloat16*>(smem + SB_W2L);
    __nv_bfloat16* uhi = reinterpret_cast<__nv_bfloat16*>(smem + SB_UHI);
    __nv_bfloat16* ulo = reinterpret_cast<__nv_bfloat16*>(smem + SB_ULO);
    float* W1e_s = reinterpret_cast<float*>(smem + SB_W1E);
    float* W1r_s = reinterpret_cast<float*>(smem + SB_W1R);
    float* be2_s = reinterpret_cast<float*>(smem + SB_BE2);
    float* rad_s = reinterpret_cast<float*>(smem + SB_RAD);
    int*   row_s = reinterpret_cast<int*>(smem + SB_ROW);
    int*   col_s = reinterpret_cast<int*>(smem + SB_COL);
    float* ea_s  = reinterpret_cast<float*>(smem + SB_EA);

    const int t = threadIdx.x;
    const int w = t >> 5, lane = t & 31;

    // stage W2^T hi/lo (once per persistent block): We2 is [k][c] -> w2*[c][k]
    for (int i = t; i < 16384; i += 512) {
        const int k = i >> 7, c = i & 127;
        const float v = We2[i];
        const __nv_bfloat16 hi = __float2bfloat16(v);
        w2h[c * BSTRIDE + k] = hi;
        w2l[c * BSTRIDE + k] = __float2bfloat16(v - __bfloat162float(hi));
    }
    for (int i = t; i < 2048; i += 512) W1e_s[i] = We1[257 * 128 + i];
    if (t < 128) {
        W1r_s[t] = We1[256 * 128 + t];
        be2_s[t] = be2[t];
    }

    // Phase-B warp tiling: warp -> m16 (edges) x n64 (cols)
    const int mt = w & 7;        // 8 m-tiles of 16 edges
    const int nh = w >> 3;       // 2 n-halves of 64 cols
    const int g  = lane >> 2;    // 0..7
    const int tq = lane & 3;     // 0..3

    for (int tile = blockIdx.x; tile < NUM_ETILES; tile += gridDim.x) {
        const int e0 = tile * ETILE;
        __syncthreads();   // guard smem tile buffers vs previous iteration readers

        for (int i = t; i < 2048; i += 512) ea_s[i] = ea[(size_t)e0 * 16 + i];
        if (t < 128) {
            const int eg = e0 + t;
            const int r = g_row[eg];
            const int c = g_col[eg];
            row_s[t] = r;
            col_s[t] = c;
            const float dx = x[r * 3 + 0] - x[c * 3 + 0];
            const float dy = x[r * 3 + 1] - x[c * 3 + 1];
            const float dz = x[r * 3 + 2] - x[c * 3 + 2];
            rad_s[t] = dx * dx + dy * dy + dz * dz;
        }
        __syncthreads();

        // ---- Phase A: u = silu(hA[row]+hB[col]+rad*W1r+ea@W1e); split hi/lo bf16 -> smem
        {
            const int ebase = w * 8;
            const int co    = lane * 4;
            float4 a4 = *reinterpret_cast<const float4*>(g_hAB + (size_t)row_s[ebase] * 256 + co);
            float4 b4 = *reinterpret_cast<const float4*>(g_hAB + (size_t)col_s[ebase] * 256 + 128 + co);
#pragma unroll
            for (int ii = 0; ii < 8; ii++) {
                float4 na, nb;
                if (ii < 7) {
                    na = *reinterpret_cast<const float4*>(g_hAB + (size_t)row_s[ebase + ii + 1] * 256 + co);
                    nb = *reinterpret_cast<const float4*>(g_hAB + (size_t)col_s[ebase + ii + 1] * 256 + 128 + co);
                }
                const int e = ebase + ii;
                const float rad = rad_s[e];
                const float4 wr = *reinterpret_cast<const float4*>(W1r_s + co);
                float tx = fmaf(rad, wr.x, a4.x + b4.x);
                float ty = fmaf(rad, wr.y, a4.y + b4.y);
                float tz = fmaf(rad, wr.z, a4.z + b4.z);
                float tw = fmaf(rad, wr.w, a4.w + b4.w);
#pragma unroll
                for (int j = 0; j < 16; j++) {
                    const float ej = ea_s[e * 16 + j];
                    const float4 wv = *reinterpret_cast<const float4*>(W1e_s + j * 128 + co);
                    tx = fmaf(ej, wv.x, tx);
                    ty = fmaf(ej, wv.y, ty);
                    tz = fmaf(ej, wv.z, tz);
                    tw = fmaf(ej, wv.w, tw);
                }
                const float sx = silu_f(tx), sy = silu_f(ty);
                const float sz = silu_f(tz), sw = silu_f(tw);
                const __nv_bfloat16 hx = __float2bfloat16(sx);
                const __nv_bfloat16 hy = __float2bfloat16(sy);
                const __nv_bfloat16 hz = __float2bfloat16(sz);
                const __nv_bfloat16 hw = __float2bfloat16(sw);
                __nv_bfloat162 hp0; hp0.x = hx; hp0.y = hy;
                __nv_bfloat162 hp1; hp1.x = hz; hp1.y = hw;
                uint2 hv;
                hv.x = *reinterpret_cast<uint32_t*>(&hp0);
                hv.y = *reinterpret_cast<uint32_t*>(&hp1);
                *reinterpret_cast<uint2*>(uhi + e * BSTRIDE + co) = hv;
                __nv_bfloat162 lp0;
                lp0.x = __float2bfloat16(sx - __bfloat162float(hx));
                lp0.y = __float2bfloat16(sy - __bfloat162float(hy));
                __nv_bfloat162 lp1;
                lp1.x = __float2bfloat16(sz - __bfloat162float(hz));
                lp1.y = __float2bfloat16(sw - __bfloat162float(hw));
                uint2 lv;
                lv.x = *reinterpret_cast<uint32_t*>(&lp0);
                lv.y = *reinterpret_cast<uint32_t*>(&lp1);
                *reinterpret_cast<uint2*>(ulo + e * BSTRIDE + co) = lv;
                if (ii < 7) { a4 = na; b4 = nb; }
            }
        }
        __syncthreads();

        // ---- Phase B: D = u_hi@W_hi + u_lo@W_hi + u_hi@W_lo via bf16 mma.sync
        {
            float d[8][4];
#pragma unroll
            for (int nt = 0; nt < 8; nt++)
#pragma unroll
                for (int j = 0; j < 4; j++) d[nt][j] = 0.f;

#pragma unroll
            for (int term = 0; term < 3; term++) {
                const __nv_bfloat16* A = (term == 1) ? ulo : uhi;
                const __nv_bfloat16* B = (term == 2) ? w2l : w2h;
                const __nv_bfloat16* Ar0 = A + (mt * 16 + g) * BSTRIDE + 2 * tq;
                const __nv_bfloat16* Ar1 = Ar0 + 8 * BSTRIDE;
                const __nv_bfloat16* Bb  = B + (nh * 64 + g) * BSTRIDE + 2 * tq;
#pragma unroll
                for (int ks = 0; ks < 8; ks++) {
                    const int kb = ks * 16;
                    const uint32_t a0 = *reinterpret_cast<const uint32_t*>(Ar0 + kb);
                    const uint32_t a1 = *reinterpret_cast<const uint32_t*>(Ar1 + kb);
                    const uint32_t a2 = *reinterpret_cast<const uint32_t*>(Ar0 + kb + 8);
                    const uint32_t a3 = *reinterpret_cast<const uint32_t*>(Ar1 + kb + 8);
#pragma unroll
                    for (int nt = 0; nt < 8; nt++) {
                        const __nv_bfloat16* Bp = Bb + nt * 8 * BSTRIDE + kb;
                        const uint32_t b0 = *reinterpret_cast<const uint32_t*>(Bp);
                        const uint32_t b1 = *reinterpret_cast<const uint32_t*>(Bp + 8);
                        mma_bf16(d[nt], a0, a1, a2, a3, b0, b1);
                    }
                }
            }

            // epilogue: silu(+bias), shfl-pair with tq^1 to form 4 contiguous cols,
            // then ONE red.v4 per thread per n-tile (32 atomics/edge, was 64).
            const int er0 = row_s[mt * 16 + g];
            const int er1 = row_s[mt * 16 + g + 8];
            const bool evenq = (tq & 1) == 0;
#pragma unroll
            for (int nt = 0; nt < 8; nt++) {
                const int col = nh * 64 + nt * 8 + 2 * tq;
                const float b0v = be2_s[col];
                const float b1v = be2_s[col + 1];
                const float v00 = silu_f(d[nt][0] + b0v);   // row g,   col, col+1
                const float v01 = silu_f(d[nt][1] + b1v);
                const float v10 = silu_f(d[nt][2] + b0v);   // row g+8, col, col+1
                const float v11 = silu_f(d[nt][3] + b1v);
                // exchange both row-pairs with partner tq^1
                const float p00 = __shfl_xor_sync(0xffffffffu, v00, 1);
                const float p01 = __shfl_xor_sync(0xffffffffu, v01, 1);
                const float p10 = __shfl_xor_sync(0xffffffffu, v10, 1);
                const float p11 = __shfl_xor_sync(0xffffffffu, v11, 1);
                const int colbase = nh * 64 + nt * 8 + (tq & 2) * 2;  // 4-aligned
                if (evenq) {
                    // row g, cols [colbase..colbase+3] = own(v00,v01) | partner(v00,v01)
                    asm volatile("red.global.add.v4.f32 [%0], {%1, %2, %3, %4};"
                                 :: "l"(g_agg + (size_t)er0 * 128 + colbase),
                                    "f"(v00), "f"(v01), "f"(p00), "f"(p01) : "memory");
                } else {
                    // row g+8, cols [colbase..colbase+3] = partner(v10,v11) | own(v10,v11)
                    asm volatile("red.global.add.v4.f32 [%0], {%1, %2, %3, %4};"
                                 :: "l"(g_agg + (size_t)er1 * 128 + colbase),
                                    "f"(p10), "f"(p11), "f"(v10), "f"(v11) : "memory");
                }
            }
        }
    }
}

// ---------------- node MLP + residual + pooled scatter (launch #5) ----------------
#define NODE_SMEM_FLOATS (256 * 36 + 128 * 33 + 32)
#define NODE_SMEM_BYTES  (NODE_SMEM_FLOATS * 4)

__global__ __launch_bounds__(256) void k_node(const float* __restrict__ h,
                                              const float* __restrict__ Wn1,
                                              const float* __restrict__ bn1,
                                              const float* __restrict__ Wn2,
                                              const float* __restrict__ bn2) {
    extern __shared__ float sm[];
    float* a_s = sm;
    float* m_s = sm + 256 * 36;
    int*   b_s = reinterpret_cast<int*>(sm + 256 * 36 + 128 * 33);

    const int n0 = blockIdx.x * NTILE;
    const int t = threadIdx.x;
    {
        const int n  = t >> 3;
        const int k4 = t & 7;
        const int ng = n0 + n;
#pragma unroll
        for (int j = 0; j < 4; j++) {
            const int k = k4 * 16 + j * 4;
            float4 v = make_float4(0.f, 0.f, 0.f, 0.f);
            float4 w = make_float4(0.f, 0.f, 0.f, 0.f);
            if (ng < N_NODES) {
                v = *reinterpret_cast<const float4*>(h + (size_t)ng * 128 + k);
                w = *reinterpret_cast<const float4*>(g_agg + (size_t)ng * 128 + k);
            }
            a_s[(k + 0) * 36 + n] = v.x;
            a_s[(k + 1) * 36 + n] = v.y;
            a_s[(k + 2) * 36 + n] = v.z;
            a_s[(k + 3) * 36 + n] = v.w;
            a_s[(128 + k + 0) * 36 + n] = w.x;
            a_s[(128 + k + 1) * 36 + n] = w.y;
            a_s[(128 + k + 2) * 36 + n] = w.z;
            a_s[(128 + k + 3) * 36 + n] = w.w;
        }
        if (t < 32) b_s[t] = (n0 + t < N_NODES) ? g_batch[n0 + t] : 0;
    }
    __syncthreads();

    const int cg = t & 31;
    const int ng = t >> 5;
    float acc[4][4];
#pragma unroll
    for (int i = 0; i < 4; i++)
#pragma unroll
        for (int j = 0; j < 4; j++) acc[i][j] = 0.f;

    for (int k = 0; k < 256; k++) {
        float av[4];
#pragma unroll
        for (int i = 0; i < 4; i++) av[i] = a_s[k * 36 + ng * 4 + i];
        const float4 w = __ldg(reinterpret_cast<const float4*>(Wn1 + k * 128 + cg * 4));
        const float wv[4] = {w.x, w.y, w.z, w.w};
#pragma unroll
        for (int i = 0; i < 4; i++)
#pragma unroll
            for (int j = 0; j < 4; j++) acc[i][j] = fmaf(av[i], wv[j], acc[i][j]);
    }
#pragma unroll
    for (int j = 0; j < 4; j++) {
        const int c = cg * 4 + j;
        const float b = __ldg(bn1 + c);
#pragma unroll
        for (int i = 0; i < 4; i++)
            m_s[c * 33 + ng * 4 + i] = silu_f(acc[i][j] + b);
    }
    __syncthreads();

    float acc2[4][4];
#pragma unroll
    for (int i = 0; i < 4; i++)
#pragma unroll
        for (int j = 0; j < 4; j++) acc2[i][j] = 0.f;

    for (int k = 0; k < 128; k++) {
        float av[4];
#pragma unroll
        for (int i = 0; i < 4; i++) av[i] = m_s[k * 33 + ng * 4 + i];
        const float4 w = __ldg(reinterpret_cast<const float4*>(Wn2 + k * 128 + cg * 4));
        const float wv[4] = {w.x, w.y, w.z, w.w};
#pragma unroll
        for (int i = 0; i < 4; i++)
#pragma unroll
            for (int j = 0; j < 4; j++) acc2[i][j] = fmaf(av[i], wv[j], acc2[i][j]);
    }
#pragma unroll
    for (int i = 0; i < 4; i++) {
        const int n = n0 + ng * 4 + i;
        if (n < N_NODES) {
            const int b = b_s[ng * 4 + i];
#pragma unroll
            for (int j = 0; j < 4; j++) {
                const int c = cg * 4 + j;
                const float hn = acc2[i][j] + __ldg(bn2 + c) + a_s[c * 36 + ng * 4 + i];
                atomicAdd(&g_pool[b * 128 + c], hn);
            }
        }
    }
    if (t < 32 && n0 + t < N_NODES) atomicAdd(&g_cnt[b_s[t]], 1.0f);
}

__global__ void k_pool_final(float* __restrict__ out) {
    const int g = blockIdx.x;
    const int c = threadIdx.x;
    const float cnt = fmaxf(g_cnt[g], 1.0f);
    out[g * 128 + c] = g_pool[g * 128 + c] / cnt;
}

// ---------------- launcher ----------------
extern "C" void kernel_launch(void* const* d_in, const int* in_sizes, int n_in,
                              void* d_out, int out_size) {
    const float* h   = (const float*)d_in[0];
    const void*  ei  = d_in[1];
    const float* x   = (const float*)d_in[2];
    const float* ea  = (const float*)d_in[3];
    const void*  bat = d_in[4];
    const float* We1 = (const float*)d_in[5];
    const float* be1 = (const float*)d_in[6];
    const float* We2 = (const float*)d_in[7];
    const float* be2 = (const float*)d_in[8];
    const float* Wn1 = (const float*)d_in[9];
    const float* bn1 = (const float*)d_in[10];
    const float* Wn2 = (const float*)d_in[11];
    const float* bn2 = (const float*)d_in[12];
    float* out = (float*)d_out;

    cudaFuncSetAttribute(k_edge, cudaFuncAttributeMaxDynamicSharedMemorySize, EDGE_SMEM_BYTES);
    cudaFuncSetAttribute(k_node, cudaFuncAttributeMaxDynamicSharedMemorySize, NODE_SMEM_BYTES);

    k_init<<<(N_NODES * HID / 4 + 255) / 256, 256>>>(ei);                       // #1
    k_cvt_idx<<<(N_EDGES + 255) / 256, 256>>>(ei, bat);                         // #2
    k_node_pre<<<(N_NODES + NTILE - 1) / NTILE, 256>>>(h, We1, be1);            // #3
    k_edge<<<152, 512, EDGE_SMEM_BYTES>>>(x, ea, We1, We2, be2);                // #4 (ncu slot)
    k_node<<<(N_NODES + NTILE - 1) / NTILE, 256, NODE_SMEM_BYTES>>>(h, Wn1, bn1, Wn2, bn2);
    k_pool_final<<<N_GRAPHS, HID>>>(out);
}

// round 8
// speedup vs baseline: 1.4082x; 1.1347x over previous
#include <cuda_runtime.h>
#include <cuda_bf16.h>
#include <cstdint>

#define N_NODES  50000
#define N_EDGES  800000
#define HID      128
#define EDGE_D   16
#define N_GRAPHS 64

#define ETILE 128
#define NTILE 32
#define NUM_ETILES (N_EDGES / ETILE)

// ---------------- device scratch (static, no allocation) ----------------
__device__ float g_hAB[(size_t)N_NODES * 256];   // hA | hB  (51.2 MB)
__device__ float g_agg[(size_t)N_NODES * HID];   // scatter target (25.6 MB)
__device__ float g_pool[N_GRAPHS * HID];
__device__ float g_cnt[N_GRAPHS];
__device__ int   g_row[N_EDGES];
__device__ int   g_col[N_EDGES];
__device__ int   g_batch[N_NODES];
__device__ int   g_is64;

__device__ __forceinline__ float silu_f(float v) {
    return __fdividef(v, 1.0f + __expf(-v));
}

// bf16 mma m16n8k16: D += A(16x16) * B(16x8), A row-major, B col-major
__device__ __forceinline__ void mma_bf16(float* d, uint32_t a0, uint32_t a1,
                                         uint32_t a2, uint32_t a3,
                                         uint32_t b0, uint32_t b1) {
    asm volatile(
        "mma.sync.aligned.m16n8k16.row.col.f32.bf16.bf16.f32 "
        "{%0,%1,%2,%3}, {%4,%5,%6,%7}, {%8,%9}, {%0,%1,%2,%3};"
        : "+f"(d[0]), "+f"(d[1]), "+f"(d[2]), "+f"(d[3])
        : "r"(a0), "r"(a1), "r"(a2), "r"(a3), "r"(b0), "r"(b1));
}

// ---------------- init: zero agg+pool, detect index width (launch #1) ----------------
__global__ void k_init(const void* __restrict__ ei) {
    const int i = blockIdx.x * blockDim.x + threadIdx.x;
    if (i < (N_NODES * HID) / 4)
        reinterpret_cast<float4*>(g_agg)[i] = make_float4(0.f, 0.f, 0.f, 0.f);
    if (i < N_GRAPHS * HID) g_pool[i] = 0.f;
    if (i < N_GRAPHS)       g_cnt[i] = 0.f;
    if (i == 0) {
        const unsigned int* p = (const unsigned int*)ei;
        int is64 = 1;
        for (int j = 0; j < 16; j++) if (p[2 * j + 1] != 0u) is64 = 0;
        g_is64 = is64;
    }
}

// ---------------- index conversion (launch #2) ----------------
__global__ void k_cvt_idx(const void* __restrict__ ei, const void* __restrict__ batch) {
    const int i = blockIdx.x * blockDim.x + threadIdx.x;
    const bool is64 = (g_is64 != 0);
    if (i < N_EDGES) {
        if (is64) {
            const long long* p = (const long long*)ei;
            g_row[i] = (int)p[i];
            g_col[i] = (int)p[N_EDGES + i];
        } else {
            const int* p = (const int*)ei;
            g_row[i] = p[i];
            g_col[i] = p[N_EDGES + i];
        }
    }
    if (i < N_NODES) {
        if (is64) g_batch[i] = (int)((const long long*)batch)[i];
        else      g_batch[i] = ((const int*)batch)[i];
    }
}

// ---------------- node pre-GEMM (launch #3): g_hAB[n] = h[n] @ [We1a|We1b] (+be1 on cols<128)
__global__ __launch_bounds__(256) void k_node_pre(const float* __restrict__ h,
                                                  const float* __restrict__ We1,
                                                  const float* __restrict__ be1) {
    __shared__ float a_s[128 * 36];
    const int n0 = blockIdx.x * NTILE;
    const int t = threadIdx.x;
    {
        const int n  = t >> 3;
        const int k4 = t & 7;
        const int ng = n0 + n;
#pragma unroll
        for (int j = 0; j < 4; j++) {
            const int k = k4 * 16 + j * 4;
            float4 v = make_float4(0.f, 0.f, 0.f, 0.f);
            if (ng < N_NODES) v = *reinterpret_cast<const float4*>(h + (size_t)ng * 128 + k);
            a_s[(k + 0) * 36 + n] = v.x;
            a_s[(k + 1) * 36 + n] = v.y;
            a_s[(k + 2) * 36 + n] = v.z;
            a_s[(k + 3) * 36 + n] = v.w;
        }
    }
    __syncthreads();
    const int cg = t & 31;
    const int ng = t >> 5;
    const int cbase = cg * 8;
    const float* wptr = (cbase < 128) ? (We1 + cbase) : (We1 + 128 * 128 + (cbase - 128));
    float acc[4][8];
#pragma unroll
    for (int i = 0; i < 4; i++)
#pragma unroll
        for (int j = 0; j < 8; j++) acc[i][j] = 0.f;

    for (int k = 0; k < 128; k++) {
        const float4 a  = *reinterpret_cast<const float4*>(&a_s[k * 36 + ng * 4]);
        const float4 w0 = __ldg(reinterpret_cast<const float4*>(wptr + k * 128));
        const float4 w1 = __ldg(reinterpret_cast<const float4*>(wptr + k * 128 + 4));
        const float av[4] = {a.x, a.y, a.z, a.w};
        const float wv[8] = {w0.x, w0.y, w0.z, w0.w, w1.x, w1.y, w1.z, w1.w};
#pragma unroll
        for (int i = 0; i < 4; i++)
#pragma unroll
            for (int j = 0; j < 8; j++) acc[i][j] = fmaf(av[i], wv[j], acc[i][j]);
    }
    float bias[8];
#pragma unroll
    for (int j = 0; j < 8; j++) bias[j] = (cbase + j < 128) ? __ldg(be1 + cbase + j) : 0.f;
#pragma unroll
    for (int i = 0; i < 4; i++) {
        const int n = n0 + ng * 4 + i;
        if (n < N_NODES) {
            float4 o0 = make_float4(acc[i][0] + bias[0], acc[i][1] + bias[1],
                                    acc[i][2] + bias[2], acc[i][3] + bias[3]);
            float4 o1 = make_float4(acc[i][4] + bias[4], acc[i][5] + bias[5],
                                    acc[i][6] + bias[6], acc[i][7] + bias[7]);
            *reinterpret_cast<float4*>(g_hAB + (size_t)n * 256 + cbase)     = o0;
            *reinterpret_cast<float4*>(g_hAB + (size_t)n * 256 + cbase + 4) = o1;
        }
    }
}

// ---------------- fused edge kernel (launch #4; persistent, 512 thr, bf16 mma 3-term) ----
#define SB_W2H   0                 // 128x136 bf16 = 34816 B  (W2^T hi, [c][k])
#define SB_W2L   34816             // 34816 B                 (W2^T lo)
#define SB_UHI   69632             // 34816 B                 (u hi, [e][k])
#define SB_ULO   104448            // 34816 B                 (u lo)
#define SB_W1E   139264            // 2048 f32 = 8192 B
#define SB_W1R   147456            // 128 f32
#define SB_BE2   147968            // 128 f32
#define SB_RAD   148480            // 128 f32
#define SB_ROW   148992            // 128 int
#define SB_COL   149504            // 128 int
#define SB_EA    150016            // 2048 f32 = 8192 B
#define EDGE_SMEM_BYTES 158208

#define BSTRIDE 136   // bf16 elements per row (272 B) -> banks 4g+tq, conflict-free

__global__ __launch_bounds__(512, 1) void k_edge(const float* __restrict__ x,
                                                 const float* __restrict__ ea,
                                                 const float* __restrict__ We1,
                                                 const float* __restrict__ We2,
                                                 const float* __restrict__ be2) {
    extern __shared__ char smem[];
    __nv_bfloat16* w2h = reinterpret_cast<__nv_bfloat16*>(smem + SB_W2H);
    __nv_bfloat16* w2l = reinterpret_cast<__nv_bfloat16*>(smem + SB_W2L);
    __nv_bfloat16* uhi = reinterpret_cast<__nv_bfloat16*>(smem + SB_UHI);
    __nv_bfloat16* ulo = reinterpret_cast<__nv_bfloat16*>(smem + SB_ULO);
    float* W1e_s = reinterpret_cast<float*>(smem + SB_W1E);
    float* W1r_s = reinterpret_cast<float*>(smem + SB_W1R);
    float* be2_s = reinterpret_cast<float*>(smem + SB_BE2);
    float* rad_s = reinterpret_cast<float*>(smem + SB_RAD);
    int*   row_s = reinterpret_cast<int*>(smem + SB_ROW);
    int*   col_s = reinterpret_cast<int*>(smem + SB_COL);
    float* ea_s  = reinterpret_cast<float*>(smem + SB_EA);

    const int t = threadIdx.x;
    const int w = t >> 5, lane = t & 31;

    // stage W2^T hi/lo (once per persistent block): We2 is [k][c] -> w2*[c][k]
    for (int i = t; i < 16384; i += 512) {
        const int k = i >> 7, c = i & 127;
        const float v = We2[i];
        const __nv_bfloat16 hi = __float2bfloat16(v);
        w2h[c * BSTRIDE + k] = hi;
        w2l[c * BSTRIDE + k] = __float2bfloat16(v - __bfloat162float(hi));
    }
    for (int i = t; i < 2048; i += 512) W1e_s[i] = We1[257 * 128 + i];
    if (t < 128) {
        W1r_s[t] = We1[256 * 128 + t];
        be2_s[t] = be2[t];
    }

    // Phase-B warp tiling: warp -> m32 (edges) x n32 (cols)
    const int mt2 = w & 3;       // 4 m-tiles of 32 edges (2 x m16)
    const int nq2 = w >> 2;      // 4 n-tiles of 32 cols  (4 x n8)
    const int g   = lane >> 2;   // 0..7
    const int tq  = lane & 3;    // 0..3

    for (int tile = blockIdx.x; tile < NUM_ETILES; tile += gridDim.x) {
        const int e0 = tile * ETILE;
        __syncthreads();   // guard smem tile buffers vs previous iteration readers

        for (int i = t; i < 2048; i += 512) ea_s[i] = ea[(size_t)e0 * 16 + i];
        if (t < 128) {
            const int eg = e0 + t;
            const int r = g_row[eg];
            const int c = g_col[eg];
            row_s[t] = r;
            col_s[t] = c;
            const float dx = x[r * 3 + 0] - x[c * 3 + 0];
            const float dy = x[r * 3 + 1] - x[c * 3 + 1];
            const float dz = x[r * 3 + 2] - x[c * 3 + 2];
            rad_s[t] = dx * dx + dy * dy + dz * dz;
        }
        __syncthreads();

        // ---- Phase A: u = silu(hA[row]+hB[col]+rad*W1r+ea@W1e); split hi/lo bf16 -> smem
        // Loop-inverted: W1e fragments cached in registers, swept across 8 edges.
        {
            const int ebase = w * 8;
            const int co    = lane * 4;
            float acc[8][4];
            const float4 wr = *reinterpret_cast<const float4*>(W1r_s + co);
#pragma unroll
            for (int ii = 0; ii < 8; ii++) {
                const int e = ebase + ii;
                const float4 a4 = *reinterpret_cast<const float4*>(g_hAB + (size_t)row_s[e] * 256 + co);
                const float4 b4 = *reinterpret_cast<const float4*>(g_hAB + (size_t)col_s[e] * 256 + 128 + co);
                const float rad = rad_s[e];
                acc[ii][0] = fmaf(rad, wr.x, a4.x + b4.x);
                acc[ii][1] = fmaf(rad, wr.y, a4.y + b4.y);
                acc[ii][2] = fmaf(rad, wr.z, a4.z + b4.z);
                acc[ii][3] = fmaf(rad, wr.w, a4.w + b4.w);
            }
#pragma unroll
            for (int jb = 0; jb < 4; jb++) {
                float4 wv[4];
#pragma unroll
                for (int q = 0; q < 4; q++)
                    wv[q] = *reinterpret_cast<const float4*>(W1e_s + (jb * 4 + q) * 128 + co);
#pragma unroll
                for (int ii = 0; ii < 8; ii++) {
                    const float4 e4 = *reinterpret_cast<const float4*>(ea_s + (ebase + ii) * 16 + jb * 4);
                    const float ev[4] = {e4.x, e4.y, e4.z, e4.w};
#pragma unroll
                    for (int q = 0; q < 4; q++) {
                        acc[ii][0] = fmaf(ev[q], wv[q].x, acc[ii][0]);
                        acc[ii][1] = fmaf(ev[q], wv[q].y, acc[ii][1]);
                        acc[ii][2] = fmaf(ev[q], wv[q].z, acc[ii][2]);
                        acc[ii][3] = fmaf(ev[q], wv[q].w, acc[ii][3]);
                    }
                }
            }
#pragma unroll
            for (int ii = 0; ii < 8; ii++) {
                const int e = ebase + ii;
                const float sx = silu_f(acc[ii][0]), sy = silu_f(acc[ii][1]);
                const float sz = silu_f(acc[ii][2]), sw = silu_f(acc[ii][3]);
                const __nv_bfloat16 hx = __float2bfloat16(sx);
                const __nv_bfloat16 hy = __float2bfloat16(sy);
                const __nv_bfloat16 hz = __float2bfloat16(sz);
                const __nv_bfloat16 hw = __float2bfloat16(sw);
                __nv_bfloat162 hp0; hp0.x = hx; hp0.y = hy;
                __nv_bfloat162 hp1; hp1.x = hz; hp1.y = hw;
                uint2 hv;
                hv.x = *reinterpret_cast<uint32_t*>(&hp0);
                hv.y = *reinterpret_cast<uint32_t*>(&hp1);
                *reinterpret_cast<uint2*>(uhi + e * BSTRIDE + co) = hv;
                __nv_bfloat162 lp0;
                lp0.x = __float2bfloat16(sx - __bfloat162float(hx));
                lp0.y = __float2bfloat16(sy - __bfloat162float(hy));
                __nv_bfloat162 lp1;
                lp1.x = __float2bfloat16(sz - __bfloat162float(hz));
                lp1.y = __float2bfloat16(sw - __bfloat162float(hw));
                uint2 lv;
                lv.x = *reinterpret_cast<uint32_t*>(&lp0);
                lv.y = *reinterpret_cast<uint32_t*>(&lp1);
                *reinterpret_cast<uint2*>(ulo + e * BSTRIDE + co) = lv;
            }
        }
        __syncthreads();

        // ---- Phase B (m32xn32 warp tile): D = u_hi@W_hi + u_lo@W_hi + u_hi@W_lo.
        // w2h fragments loaded ONCE per ks and reused for both A_hi and A_lo terms.
        {
            float d[2][4][4];
#pragma unroll
            for (int mi = 0; mi < 2; mi++)
#pragma unroll
                for (int nt = 0; nt < 4; nt++)
#pragma unroll
                    for (int j = 0; j < 4; j++) d[mi][nt][j] = 0.f;

            const int arow = mt2 * 32 + g;
            const int brow = nq2 * 32 + g;
#pragma unroll
            for (int ks = 0; ks < 8; ks++) {
                const int kb = ks * 16;
                uint32_t ah[2][4], al[2][4];
#pragma unroll
                for (int mi = 0; mi < 2; mi++) {
                    const __nv_bfloat16* Ah = uhi + (arow + mi * 16) * BSTRIDE + 2 * tq + kb;
                    ah[mi][0] = *reinterpret_cast<const uint32_t*>(Ah);
                    ah[mi][1] = *reinterpret_cast<const uint32_t*>(Ah + 8 * BSTRIDE);
                    ah[mi][2] = *reinterpret_cast<const uint32_t*>(Ah + 8);
                    ah[mi][3] = *reinterpret_cast<const uint32_t*>(Ah + 8 * BSTRIDE + 8);
                    const __nv_bfloat16* Al = ulo + (arow + mi * 16) * BSTRIDE + 2 * tq + kb;
                    al[mi][0] = *reinterpret_cast<const uint32_t*>(Al);
                    al[mi][1] = *reinterpret_cast<const uint32_t*>(Al + 8 * BSTRIDE);
                    al[mi][2] = *reinterpret_cast<const uint32_t*>(Al + 8);
                    al[mi][3] = *reinterpret_cast<const uint32_t*>(Al + 8 * BSTRIDE + 8);
                }
                uint32_t bf[4][2];
#pragma unroll
                for (int nt = 0; nt < 4; nt++) {
                    const __nv_bfloat16* Bp = w2h + (brow + nt * 8) * BSTRIDE + 2 * tq + kb;
                    bf[nt][0] = *reinterpret_cast<const uint32_t*>(Bp);
                    bf[nt][1] = *reinterpret_cast<const uint32_t*>(Bp + 8);
                }
#pragma unroll
                for (int nt = 0; nt < 4; nt++)
#pragma unroll
                    for (int mi = 0; mi < 2; mi++) {
                        mma_bf16(d[mi][nt], ah[mi][0], ah[mi][1], ah[mi][2], ah[mi][3],
                                 bf[nt][0], bf[nt][1]);
                        mma_bf16(d[mi][nt], al[mi][0], al[mi][1], al[mi][2], al[mi][3],
                                 bf[nt][0], bf[nt][1]);
                    }
#pragma unroll
                for (int nt = 0; nt < 4; nt++) {
                    const __nv_bfloat16* Bp = w2l + (brow + nt * 8) * BSTRIDE + 2 * tq + kb;
                    bf[nt][0] = *reinterpret_cast<const uint32_t*>(Bp);
                    bf[nt][1] = *reinterpret_cast<const uint32_t*>(Bp + 8);
                }
#pragma unroll
                for (int nt = 0; nt < 4; nt++)
#pragma unroll
                    for (int mi = 0; mi < 2; mi++)
                        mma_bf16(d[mi][nt], ah[mi][0], ah[mi][1], ah[mi][2], ah[mi][3],
                                 bf[nt][0], bf[nt][1]);
            }

            // epilogue: silu(+bias), shfl-pair with tq^1, one red.v4 per thread per (mi,nt)
            const bool evenq = (tq & 1) == 0;
#pragma unroll
            for (int mi = 0; mi < 2; mi++) {
                const int er0 = row_s[mt2 * 32 + mi * 16 + g];
                const int er1 = row_s[mt2 * 32 + mi * 16 + g + 8];
#pragma unroll
                for (int nt = 0; nt < 4; nt++) {
                    const int col = nq2 * 32 + nt * 8 + 2 * tq;
                    const float b0v = be2_s[col];
                    const float b1v = be2_s[col + 1];
                    const float v00 = silu_f(d[mi][nt][0] + b0v);
                    const float v01 = silu_f(d[mi][nt][1] + b1v);
                    const float v10 = silu_f(d[mi][nt][2] + b0v);
                    const float v11 = silu_f(d[mi][nt][3] + b1v);
                    const float p00 = __shfl_xor_sync(0xffffffffu, v00, 1);
                    const float p01 = __shfl_xor_sync(0xffffffffu, v01, 1);
                    const float p10 = __shfl_xor_sync(0xffffffffu, v10, 1);
                    const float p11 = __shfl_xor_sync(0xffffffffu, v11, 1);
                    const int colbase = nq2 * 32 + nt * 8 + (tq & 2) * 2;
                    if (evenq) {
                        asm volatile("red.global.add.v4.f32 [%0], {%1, %2, %3, %4};"
                                     :: "l"(g_agg + (size_t)er0 * 128 + colbase),
                                        "f"(v00), "f"(v01), "f"(p00), "f"(p01) : "memory");
                    } else {
                        asm volatile("red.global.add.v4.f32 [%0], {%1, %2, %3, %4};"
                                     :: "l"(g_agg + (size_t)er1 * 128 + colbase),
                                        "f"(p10), "f"(p11), "f"(v10), "f"(v11) : "memory");
                    }
                }
            }
        }
    }
}

// ---------------- node MLP + residual + pooled scatter (launch #5) ----------------
#define NODE_SMEM_FLOATS (256 * 36 + 128 * 33 + 32)
#define NODE_SMEM_BYTES  (NODE_SMEM_FLOATS * 4)

__global__ __launch_bounds__(256) void k_node(const float* __restrict__ h,
                                              const float* __restrict__ Wn1,
                                              const float* __restrict__ bn1,
                                              const float* __restrict__ Wn2,
                                              const float* __restrict__ bn2) {
    extern __shared__ float sm[];
    float* a_s = sm;
    float* m_s = sm + 256 * 36;
    int*   b_s = reinterpret_cast<int*>(sm + 256 * 36 + 128 * 33);

    const int n0 = blockIdx.x * NTILE;
    const int t = threadIdx.x;
    {
        const int n  = t >> 3;
        const int k4 = t & 7;
        const int ng = n0 + n;
#pragma unroll
        for (int j = 0; j < 4; j++) {
            const int k = k4 * 16 + j * 4;
            float4 v = make_float4(0.f, 0.f, 0.f, 0.f);
            float4 w = make_float4(0.f, 0.f, 0.f, 0.f);
            if (ng < N_NODES) {
                v = *reinterpret_cast<const float4*>(h + (size_t)ng * 128 + k);
                w = *reinterpret_cast<const float4*>(g_agg + (size_t)ng * 128 + k);
            }
            a_s[(k + 0) * 36 + n] = v.x;
            a_s[(k + 1) * 36 + n] = v.y;
            a_s[(k + 2) * 36 + n] = v.z;
            a_s[(k + 3) * 36 + n] = v.w;
            a_s[(128 + k + 0) * 36 + n] = w.x;
            a_s[(128 + k + 1) * 36 + n] = w.y;
            a_s[(128 + k + 2) * 36 + n] = w.z;
            a_s[(128 + k + 3) * 36 + n] = w.w;
        }
        if (t < 32) b_s[t] = (n0 + t < N_NODES) ? g_batch[n0 + t] : 0;
    }
    __syncthreads();

    const int cg = t & 31;
    const int ng = t >> 5;
    float acc[4][4];
#pragma unroll
    for (int i = 0; i < 4; i++)
#pragma unroll
        for (int j = 0; j < 4; j++) acc[i][j] = 0.f;

    for (int k = 0; k < 256; k++) {
        float av[4];
#pragma unroll
        for (int i = 0; i < 4; i++) av[i] = a_s[k * 36 + ng * 4 + i];
        const float4 w = __ldg(reinterpret_cast<const float4*>(Wn1 + k * 128 + cg * 4));
        const float wv[4] = {w.x, w.y, w.z, w.w};
#pragma unroll
        for (int i = 0; i < 4; i++)
#pragma unroll
            for (int j = 0; j < 4; j++) acc[i][j] = fmaf(av[i], wv[j], acc[i][j]);
    }
#pragma unroll
    for (int j = 0; j < 4; j++) {
        const int c = cg * 4 + j;
        const float b = __ldg(bn1 + c);
#pragma unroll
        for (int i = 0; i < 4; i++)
            m_s[c * 33 + ng * 4 + i] = silu_f(acc[i][j] + b);
    }
    __syncthreads();

    float acc2[4][4];
#pragma unroll
    for (int i = 0; i < 4; i++)
#pragma unroll
        for (int j = 0; j < 4; j++) acc2[i][j] = 0.f;

    for (int k = 0; k < 128; k++) {
        float av[4];
#pragma unroll
        for (int i = 0; i < 4; i++) av[i] = m_s[k * 33 + ng * 4 + i];
        const float4 w = __ldg(reinterpret_cast<const float4*>(Wn2 + k * 128 + cg * 4));
        const float wv[4] = {w.x, w.y, w.z, w.w};
#pragma unroll
        for (int i = 0; i < 4; i++)
#pragma unroll
            for (int j = 0; j < 4; j++) acc2[i][j] = fmaf(av[i], wv[j], acc2[i][j]);
    }
#pragma unroll
    for (int i = 0; i < 4; i++) {
        const int n = n0 + ng * 4 + i;
        if (n < N_NODES) {
            const int b = b_s[ng * 4 + i];
#pragma unroll
            for (int j = 0; j < 4; j++) {
                const int c = cg * 4 + j;
                const float hn = acc2[i][j] + __ldg(bn2 + c) + a_s[c * 36 + ng * 4 + i];
                atomicAdd(&g_pool[b * 128 + c], hn);
            }
        }
    }
    if (t < 32 && n0 + t < N_NODES) atomicAdd(&g_cnt[b_s[t]], 1.0f);
}

__global__ void k_pool_final(float* __restrict__ out) {
    const int g = blockIdx.x;
    const int c = threadIdx.x;
    const float cnt = fmaxf(g_cnt[g], 1.0f);
    out[g * 128 + c] = g_pool[g * 128 + c] / cnt;
}

// ---------------- launcher ----------------
extern "C" void kernel_launch(void* const* d_in, const int* in_sizes, int n_in,
                              void* d_out, int out_size) {
    const float* h   = (const float*)d_in[0];
    const void*  ei  = d_in[1];
    const float* x   = (const float*)d_in[2];
    const float* ea  = (const float*)d_in[3];
    const void*  bat = d_in[4];
    const float* We1 = (const float*)d_in[5];
    const float* be1 = (const float*)d_in[6];
    const float* We2 = (const float*)d_in[7];
    const float* be2 = (const float*)d_in[8];
    const float* Wn1 = (const float*)d_in[9];
    const float* bn1 = (const float*)d_in[10];
    const float* Wn2 = (const float*)d_in[11];
    const float* bn2 = (const float*)d_in[12];
    float* out = (float*)d_out;

    cudaFuncSetAttribute(k_edge, cudaFuncAttributeMaxDynamicSharedMemorySize, EDGE_SMEM_BYTES);
    cudaFuncSetAttribute(k_node, cudaFuncAttributeMaxDynamicSharedMemorySize, NODE_SMEM_BYTES);

    k_init<<<(N_NODES * HID / 4 + 255) / 256, 256>>>(ei);                       // #1
    k_cvt_idx<<<(N_EDGES + 255) / 256, 256>>>(ei, bat);                         // #2
    k_node_pre<<<(N_NODES + NTILE - 1) / NTILE, 256>>>(h, We1, be1);            // #3
    k_edge<<<152, 512, EDGE_SMEM_BYTES>>>(x, ea, We1, We2, be2);                // #4 (ncu slot)
    k_node<<<(N_NODES + NTILE - 1) / NTILE, 256, NODE_SMEM_BYTES>>>(h, Wn1, bn1, Wn2, bn2);
    k_pool_final<<<N_GRAPHS, HID>>>(out);
}

// round 9
// speedup vs baseline: 1.4765x; 1.0485x over previous
#include <cuda_runtime.h>
#include <cuda_bf16.h>
#include <cstdint>

#define N_NODES  50000
#define N_EDGES  800000
#define HID      128
#define EDGE_D   16
#define N_GRAPHS 64

#define ETILE 128
#define NTILE 32
#define NUM_ETILES (N_EDGES / ETILE)
#define EGRID 152

// ---------------- device scratch (static, no allocation) ----------------
__device__ float g_hAB[(size_t)N_NODES * 256];   // hA | hB  (51.2 MB)
__device__ float g_agg[(size_t)N_NODES * HID];   // scatter target (25.6 MB)
__device__ float g_pool[N_GRAPHS * HID];
__device__ float g_cnt[N_GRAPHS];
__device__ int   g_row[N_EDGES];
__device__ int   g_col[N_EDGES];
__device__ int   g_batch[N_NODES];
__device__ int   g_is64;

__device__ __forceinline__ float silu_f(float v) {
    return __fdividef(v, 1.0f + __expf(-v));
}

// bf16 mma m16n8k16: D += A(16x16) * B(16x8), A row-major, B col-major
__device__ __forceinline__ void mma_bf16(float* d, uint32_t a0, uint32_t a1,
                                         uint32_t a2, uint32_t a3,
                                         uint32_t b0, uint32_t b1) {
    asm volatile(
        "mma.sync.aligned.m16n8k16.row.col.f32.bf16.bf16.f32 "
        "{%0,%1,%2,%3}, {%4,%5,%6,%7}, {%8,%9}, {%0,%1,%2,%3};"
        : "+f"(d[0]), "+f"(d[1]), "+f"(d[2]), "+f"(d[3])
        : "r"(a0), "r"(a1), "r"(a2), "r"(a3), "r"(b0), "r"(b1));
}

// ---------------- init: zero agg+pool, detect index width (launch #1) ----------------
__global__ void k_init(const void* __restrict__ ei) {
    const int i = blockIdx.x * blockDim.x + threadIdx.x;
    if (i < (N_NODES * HID) / 4)
        reinterpret_cast<float4*>(g_agg)[i] = make_float4(0.f, 0.f, 0.f, 0.f);
    if (i < N_GRAPHS * HID) g_pool[i] = 0.f;
    if (i < N_GRAPHS)       g_cnt[i] = 0.f;
    if (i == 0) {
        const unsigned int* p = (const unsigned int*)ei;
        int is64 = 1;
        for (int j = 0; j < 16; j++) if (p[2 * j + 1] != 0u) is64 = 0;
        g_is64 = is64;
    }
}

// ---------------- index conversion (launch #2) ----------------
__global__ void k_cvt_idx(const void* __restrict__ ei, const void* __restrict__ batch) {
    const int i = blockIdx.x * blockDim.x + threadIdx.x;
    const bool is64 = (g_is64 != 0);
    if (i < N_EDGES) {
        if (is64) {
            const long long* p = (const long long*)ei;
            g_row[i] = (int)p[i];
            g_col[i] = (int)p[N_EDGES + i];
        } else {
            const int* p = (const int*)ei;
            g_row[i] = p[i];
            g_col[i] = p[N_EDGES + i];
        }
    }
    if (i < N_NODES) {
        if (is64) g_batch[i] = (int)((const long long*)batch)[i];
        else      g_batch[i] = ((const int*)batch)[i];
    }
}

// ---------------- node pre-GEMM (launch #3): g_hAB[n] = h[n] @ [We1a|We1b] (+be1 on cols<128)
__global__ __launch_bounds__(256) void k_node_pre(const float* __restrict__ h,
                                                  const float* __restrict__ We1,
                                                  const float* __restrict__ be1) {
    __shared__ float a_s[128 * 36];
    const int n0 = blockIdx.x * NTILE;
    const int t = threadIdx.x;
    {
        const int n  = t >> 3;
        const int k4 = t & 7;
        const int ng = n0 + n;
#pragma unroll
        for (int j = 0; j < 4; j++) {
            const int k = k4 * 16 + j * 4;
            float4 v = make_float4(0.f, 0.f, 0.f, 0.f);
            if (ng < N_NODES) v = *reinterpret_cast<const float4*>(h + (size_t)ng * 128 + k);
            a_s[(k + 0) * 36 + n] = v.x;
            a_s[(k + 1) * 36 + n] = v.y;
            a_s[(k + 2) * 36 + n] = v.z;
            a_s[(k + 3) * 36 + n] = v.w;
        }
    }
    __syncthreads();
    const int cg = t & 31;
    const int ng = t >> 5;
    const int cbase = cg * 8;
    const float* wptr = (cbase < 128) ? (We1 + cbase) : (We1 + 128 * 128 + (cbase - 128));
    float acc[4][8];
#pragma unroll
    for (int i = 0; i < 4; i++)
#pragma unroll
        for (int j = 0; j < 8; j++) acc[i][j] = 0.f;

    for (int k = 0; k < 128; k++) {
        const float4 a  = *reinterpret_cast<const float4*>(&a_s[k * 36 + ng * 4]);
        const float4 w0 = __ldg(reinterpret_cast<const float4*>(wptr + k * 128));
        const float4 w1 = __ldg(reinterpret_cast<const float4*>(wptr + k * 128 + 4));
        const float av[4] = {a.x, a.y, a.z, a.w};
        const float wv[8] = {w0.x, w0.y, w0.z, w0.w, w1.x, w1.y, w1.z, w1.w};
#pragma unroll
        for (int i = 0; i < 4; i++)
#pragma unroll
            for (int j = 0; j < 8; j++) acc[i][j] = fmaf(av[i], wv[j], acc[i][j]);
    }
    float bias[8];
#pragma unroll
    for (int j = 0; j < 8; j++) bias[j] = (cbase + j < 128) ? __ldg(be1 + cbase + j) : 0.f;
#pragma unroll
    for (int i = 0; i < 4; i++) {
        const int n = n0 + ng * 4 + i;
        if (n < N_NODES) {
            float4 o0 = make_float4(acc[i][0] + bias[0], acc[i][1] + bias[1],
                                    acc[i][2] + bias[2], acc[i][3] + bias[3]);
            float4 o1 = make_float4(acc[i][4] + bias[4], acc[i][5] + bias[5],
                                    acc[i][6] + bias[6], acc[i][7] + bias[7]);
            *reinterpret_cast<float4*>(g_hAB + (size_t)n * 256 + cbase)     = o0;
            *reinterpret_cast<float4*>(g_hAB + (size_t)n * 256 + cbase + 4) = o1;
        }
    }
}

// ---------------- fused edge kernel (launch #4; persistent, software-pipelined) ----------
// smem: W2 hi/lo + DOUBLE-BUFFERED u hi/lo + W1e/W1r/be2. One barrier per tile:
// region = { PhaseA(t+1) -> buf[nxt]; PhaseB(t) <- buf[cur] } so FMA and tensor
// pipes overlap across warps.
#define SB_W2H   0                 // 34816 B  (W2^T hi, [c][k], stride 136)
#define SB_W2L   34816             // 34816 B
#define SB_U0H   69632             // 34816 B  u hi buf0
#define SB_U0L   104448            // 34816 B  u lo buf0
#define SB_U1H   139264            // 34816 B  u hi buf1
#define SB_U1L   174080            // 34816 B  u lo buf1
#define SB_W1E   208896            // 2048 f32 = 8192 B
#define SB_W1R   217088            // 128 f32 = 512 B
#define SB_BE2   217600            // 128 f32 = 512 B
#define EDGE_SMEM_BYTES 218112

#define BSTRIDE 136   // bf16 elements per row (272 B) -> banks 4g+tq, conflict-free

__device__ __forceinline__ void edge_phaseA(
    int e0, int w, int lane,
    const float* __restrict__ x, const float* __restrict__ ea,
    const float* W1e_s, float4 wr,
    __nv_bfloat16* uhi, __nv_bfloat16* ulo)
{
    const int ebase = w * 8;
    const int co    = lane * 4;
    // lanes 0..7 fetch row/col/radial for this warp's 8 edges
    int r8 = 0, c8 = 0;
    float rad8 = 0.f;
    if (lane < 8) {
        const int eg = e0 + ebase + lane;
        r8 = g_row[eg];
        c8 = g_col[eg];
        const float dx = x[r8 * 3 + 0] - x[c8 * 3 + 0];
        const float dy = x[r8 * 3 + 1] - x[c8 * 3 + 1];
        const float dz = x[r8 * 3 + 2] - x[c8 * 3 + 2];
        rad8 = dx * dx + dy * dy + dz * dz;
    }
    float acc[8][4];
#pragma unroll
    for (int ii = 0; ii < 8; ii++) {
        const int r   = __shfl_sync(0xffffffffu, r8, ii);
        const int c   = __shfl_sync(0xffffffffu, c8, ii);
        const float rad = __shfl_sync(0xffffffffu, rad8, ii);
        const float4 a4 = *reinterpret_cast<const float4*>(g_hAB + (size_t)r * 256 + co);
        const float4 b4 = *reinterpret_cast<const float4*>(g_hAB + (size_t)c * 256 + 128 + co);
        acc[ii][0] = fmaf(rad, wr.x, a4.x + b4.x);
        acc[ii][1] = fmaf(rad, wr.y, a4.y + b4.y);
        acc[ii][2] = fmaf(rad, wr.z, a4.z + b4.z);
        acc[ii][3] = fmaf(rad, wr.w, a4.w + b4.w);
    }
#pragma unroll
    for (int jb = 0; jb < 4; jb++) {
        float4 wv[4];
#pragma unroll
        for (int q = 0; q < 4; q++)
            wv[q] = *reinterpret_cast<const float4*>(W1e_s + (jb * 4 + q) * 128 + co);
#pragma unroll
        for (int ii = 0; ii < 8; ii++) {
            const float4 e4 = __ldg(reinterpret_cast<const float4*>(
                ea + (size_t)(e0 + ebase + ii) * 16 + jb * 4));
            const float ev[4] = {e4.x, e4.y, e4.z, e4.w};
#pragma unroll
            for (int q = 0; q < 4; q++) {
                acc[ii][0] = fmaf(ev[q], wv[q].x, acc[ii][0]);
                acc[ii][1] = fmaf(ev[q], wv[q].y, acc[ii][1]);
                acc[ii][2] = fmaf(ev[q], wv[q].z, acc[ii][2]);
                acc[ii][3] = fmaf(ev[q], wv[q].w, acc[ii][3]);
            }
        }
    }
#pragma unroll
    for (int ii = 0; ii < 8; ii++) {
        const int e = ebase + ii;
        const float sx = silu_f(acc[ii][0]), sy = silu_f(acc[ii][1]);
        const float sz = silu_f(acc[ii][2]), sw = silu_f(acc[ii][3]);
        const __nv_bfloat16 hx = __float2bfloat16(sx);
        const __nv_bfloat16 hy = __float2bfloat16(sy);
        const __nv_bfloat16 hz = __float2bfloat16(sz);
        const __nv_bfloat16 hw = __float2bfloat16(sw);
        __nv_bfloat162 hp0; hp0.x = hx; hp0.y = hy;
        __nv_bfloat162 hp1; hp1.x = hz; hp1.y = hw;
        uint2 hv;
        hv.x = *reinterpret_cast<uint32_t*>(&hp0);
        hv.y = *reinterpret_cast<uint32_t*>(&hp1);
        *reinterpret_cast<uint2*>(uhi + e * BSTRIDE + co) = hv;
        __nv_bfloat162 lp0;
        lp0.x = __float2bfloat16(sx - __bfloat162float(hx));
        lp0.y = __float2bfloat16(sy - __bfloat162float(hy));
        __nv_bfloat162 lp1;
        lp1.x = __float2bfloat16(sz - __bfloat162float(hz));
        lp1.y = __float2bfloat16(sw - __bfloat162float(hw));
        uint2 lv;
        lv.x = *reinterpret_cast<uint32_t*>(&lp0);
        lv.y = *reinterpret_cast<uint32_t*>(&lp1);
        *reinterpret_cast<uint2*>(ulo + e * BSTRIDE + co) = lv;
    }
}

__device__ __forceinline__ void edge_phaseB(
    int e0, int mt2, int nq2, int g, int tq,
    const __nv_bfloat16* uhi, const __nv_bfloat16* ulo,
    const __nv_bfloat16* w2h, const __nv_bfloat16* w2l,
    const float* be2_s)
{
    float d[2][4][4];
#pragma unroll
    for (int mi = 0; mi < 2; mi++)
#pragma unroll
        for (int nt = 0; nt < 4; nt++)
#pragma unroll
            for (int j = 0; j < 4; j++) d[mi][nt][j] = 0.f;

    const int arow = mt2 * 32 + g;
    const int brow = nq2 * 32 + g;
#pragma unroll
    for (int ks = 0; ks < 8; ks++) {
        const int kb = ks * 16;
        uint32_t ah[2][4], al[2][4];
#pragma unroll
        for (int mi = 0; mi < 2; mi++) {
            const __nv_bfloat16* Ah = uhi + (arow + mi * 16) * BSTRIDE + 2 * tq + kb;
            ah[mi][0] = *reinterpret_cast<const uint32_t*>(Ah);
            ah[mi][1] = *reinterpret_cast<const uint32_t*>(Ah + 8 * BSTRIDE);
            ah[mi][2] = *reinterpret_cast<const uint32_t*>(Ah + 8);
            ah[mi][3] = *reinterpret_cast<const uint32_t*>(Ah + 8 * BSTRIDE + 8);
            const __nv_bfloat16* Al = ulo + (arow + mi * 16) * BSTRIDE + 2 * tq + kb;
            al[mi][0] = *reinterpret_cast<const uint32_t*>(Al);
            al[mi][1] = *reinterpret_cast<const uint32_t*>(Al + 8 * BSTRIDE);
            al[mi][2] = *reinterpret_cast<const uint32_t*>(Al + 8);
            al[mi][3] = *reinterpret_cast<const uint32_t*>(Al + 8 * BSTRIDE + 8);
        }
        uint32_t bf[4][2];
#pragma unroll
        for (int nt = 0; nt < 4; nt++) {
            const __nv_bfloat16* Bp = w2h + (brow + nt * 8) * BSTRIDE + 2 * tq + kb;
            bf[nt][0] = *reinterpret_cast<const uint32_t*>(Bp);
            bf[nt][1] = *reinterpret_cast<const uint32_t*>(Bp + 8);
        }
#pragma unroll
        for (int nt = 0; nt < 4; nt++)
#pragma unroll
            for (int mi = 0; mi < 2; mi++) {
                mma_bf16(d[mi][nt], ah[mi][0], ah[mi][1], ah[mi][2], ah[mi][3],
                         bf[nt][0], bf[nt][1]);
                mma_bf16(d[mi][nt], al[mi][0], al[mi][1], al[mi][2], al[mi][3],
                         bf[nt][0], bf[nt][1]);
            }
#pragma unroll
        for (int nt = 0; nt < 4; nt++) {
            const __nv_bfloat16* Bp = w2l + (brow + nt * 8) * BSTRIDE + 2 * tq + kb;
            bf[nt][0] = *reinterpret_cast<const uint32_t*>(Bp);
            bf[nt][1] = *reinterpret_cast<const uint32_t*>(Bp + 8);
        }
#pragma unroll
        for (int nt = 0; nt < 4; nt++)
#pragma unroll
            for (int mi = 0; mi < 2; mi++)
                mma_bf16(d[mi][nt], ah[mi][0], ah[mi][1], ah[mi][2], ah[mi][3],
                         bf[nt][0], bf[nt][1]);
    }

    // epilogue: silu(+bias), shfl-pair with tq^1, one red.v4 per thread per (mi,nt)
    const bool evenq = (tq & 1) == 0;
#pragma unroll
    for (int mi = 0; mi < 2; mi++) {
        const int er0 = g_row[e0 + mt2 * 32 + mi * 16 + g];
        const int er1 = g_row[e0 + mt2 * 32 + mi * 16 + g + 8];
#pragma unroll
        for (int nt = 0; nt < 4; nt++) {
            const int col = nq2 * 32 + nt * 8 + 2 * tq;
            const float b0v = be2_s[col];
            const float b1v = be2_s[col + 1];
            const float v00 = silu_f(d[mi][nt][0] + b0v);
            const float v01 = silu_f(d[mi][nt][1] + b1v);
            const float v10 = silu_f(d[mi][nt][2] + b0v);
            const float v11 = silu_f(d[mi][nt][3] + b1v);
            const float p00 = __shfl_xor_sync(0xffffffffu, v00, 1);
            const float p01 = __shfl_xor_sync(0xffffffffu, v01, 1);
            const float p10 = __shfl_xor_sync(0xffffffffu, v10, 1);
            const float p11 = __shfl_xor_sync(0xffffffffu, v11, 1);
            const int colbase = nq2 * 32 + nt * 8 + (tq & 2) * 2;
            if (evenq) {
                asm volatile("red.global.add.v4.f32 [%0], {%1, %2, %3, %4};"
                             :: "l"(g_agg + (size_t)er0 * 128 + colbase),
                                "f"(v00), "f"(v01), "f"(p00), "f"(p01) : "memory");
            } else {
                asm volatile("red.global.add.v4.f32 [%0], {%1, %2, %3, %4};"
                             :: "l"(g_agg + (size_t)er1 * 128 + colbase),
                                "f"(p10), "f"(p11), "f"(v10), "f"(v11) : "memory");
            }
        }
    }
}

__global__ __launch_bounds__(512, 1) void k_edge(const float* __restrict__ x,
                                                 const float* __restrict__ ea,
                                                 const float* __restrict__ We1,
                                                 const float* __restrict__ We2,
                                                 const float* __restrict__ be2) {
    extern __shared__ char smem[];
    __nv_bfloat16* w2h = reinterpret_cast<__nv_bfloat16*>(smem + SB_W2H);
    __nv_bfloat16* w2l = reinterpret_cast<__nv_bfloat16*>(smem + SB_W2L);
    __nv_bfloat16* ubh[2] = {reinterpret_cast<__nv_bfloat16*>(smem + SB_U0H),
                             reinterpret_cast<__nv_bfloat16*>(smem + SB_U1H)};
    __nv_bfloat16* ubl[2] = {reinterpret_cast<__nv_bfloat16*>(smem + SB_U0L),
                             reinterpret_cast<__nv_bfloat16*>(smem + SB_U1L)};
    float* W1e_s = reinterpret_cast<float*>(smem + SB_W1E);
    float* W1r_s = reinterpret_cast<float*>(smem + SB_W1R);
    float* be2_s = reinterpret_cast<float*>(smem + SB_BE2);

    const int t = threadIdx.x;
    const int w = t >> 5, lane = t & 31;

    // stage loop-invariant weights once
    for (int i = t; i < 16384; i += 512) {
        const int k = i >> 7, c = i & 127;
        const float v = We2[i];
        const __nv_bfloat16 hi = __float2bfloat16(v);
        w2h[c * BSTRIDE + k] = hi;
        w2l[c * BSTRIDE + k] = __float2bfloat16(v - __bfloat162float(hi));
    }
    for (int i = t; i < 2048; i += 512) W1e_s[i] = We1[257 * 128 + i];
    if (t < 128) {
        W1r_s[t] = We1[256 * 128 + t];
        be2_s[t] = be2[t];
    }
    __syncthreads();

    const float4 wr = *reinterpret_cast<const float4*>(W1r_s + lane * 4);

    // Phase-B warp tiling: warp -> m32 x n32
    const int mt2 = w & 3;
    const int nq2 = w >> 2;
    const int g   = lane >> 2;
    const int tq  = lane & 3;

    // prologue: A(first tile) into buf 0
    const int t0 = blockIdx.x;
    if (t0 < NUM_ETILES)
        edge_phaseA(t0 * ETILE, w, lane, x, ea, W1e_s, wr, ubh[0], ubl[0]);
    __syncthreads();

    int cur = 0;
    for (int tile = t0; tile < NUM_ETILES; tile += EGRID, cur ^= 1) {
        const int tn = tile + EGRID;
        if (tn < NUM_ETILES)
            edge_phaseA(tn * ETILE, w, lane, x, ea, W1e_s, wr, ubh[cur ^ 1], ubl[cur ^ 1]);
        edge_phaseB(tile * ETILE, mt2, nq2, g, tq, ubh[cur], ubl[cur], w2h, w2l, be2_s);
        __syncthreads();
    }
}

// ---------------- node MLP + residual + pooled scatter (launch #5) ----------------
#define NODE_SMEM_FLOATS (256 * 36 + 128 * 33 + 32)
#define NODE_SMEM_BYTES  (NODE_SMEM_FLOATS * 4)

__global__ __launch_bounds__(256) void k_node(const float* __restrict__ h,
                                              const float* __restrict__ Wn1,
                                              const float* __restrict__ bn1,
                                              const float* __restrict__ Wn2,
                                              const float* __restrict__ bn2) {
    extern __shared__ float sm[];
    float* a_s = sm;
    float* m_s = sm + 256 * 36;
    int*   b_s = reinterpret_cast<int*>(sm + 256 * 36 + 128 * 33);

    const int n0 = blockIdx.x * NTILE;
    const int t = threadIdx.x;
    {
        const int n  = t >> 3;
        const int k4 = t & 7;
        const int ng = n0 + n;
#pragma unroll
        for (int j = 0; j < 4; j++) {
            const int k = k4 * 16 + j * 4;
            float4 v = make_float4(0.f, 0.f, 0.f, 0.f);
            float4 w = make_float4(0.f, 0.f, 0.f, 0.f);
            if (ng < N_NODES) {
                v = *reinterpret_cast<const float4*>(h + (size_t)ng * 128 + k);
                w = *reinterpret_cast<const float4*>(g_agg + (size_t)ng * 128 + k);
            }
            a_s[(k + 0) * 36 + n] = v.x;
            a_s[(k + 1) * 36 + n] = v.y;
            a_s[(k + 2) * 36 + n] = v.z;
            a_s[(k + 3) * 36 + n] = v.w;
            a_s[(128 + k + 0) * 36 + n] = w.x;
            a_s[(128 + k + 1) * 36 + n] = w.y;
            a_s[(128 + k + 2) * 36 + n] = w.z;
            a_s[(128 + k + 3) * 36 + n] = w.w;
        }
        if (t < 32) b_s[t] = (n0 + t < N_NODES) ? g_batch[n0 + t] : 0;
    }
    __syncthreads();

    const int cg = t & 31;
    const int ng = t >> 5;
    float acc[4][4];
#pragma unroll
    for (int i = 0; i < 4; i++)
#pragma unroll
        for (int j = 0; j < 4; j++) acc[i][j] = 0.f;

    for (int k = 0; k < 256; k++) {
        float av[4];
#pragma unroll
        for (int i = 0; i < 4; i++) av[i] = a_s[k * 36 + ng * 4 + i];
        const float4 w = __ldg(reinterpret_cast<const float4*>(Wn1 + k * 128 + cg * 4));
        const float wv[4] = {w.x, w.y, w.z, w.w};
#pragma unroll
        for (int i = 0; i < 4; i++)
#pragma unroll
            for (int j = 0; j < 4; j++) acc[i][j] = fmaf(av[i], wv[j], acc[i][j]);
    }
#pragma unroll
    for (int j = 0; j < 4; j++) {
        const int c = cg * 4 + j;
        const float b = __ldg(bn1 + c);
#pragma unroll
        for (int i = 0; i < 4; i++)
            m_s[c * 33 + ng * 4 + i] = silu_f(acc[i][j] + b);
    }
    __syncthreads();

    float acc2[4][4];
#pragma unroll
    for (int i = 0; i < 4; i++)
#pragma unroll
        for (int j = 0; j < 4; j++) acc2[i][j] = 0.f;

    for (int k = 0; k < 128; k++) {
        float av[4];
#pragma unroll
        for (int i = 0; i < 4; i++) av[i] = m_s[k * 33 + ng * 4 + i];
        const float4 w = __ldg(reinterpret_cast<const float4*>(Wn2 + k * 128 + cg * 4));
        const float wv[4] = {w.x, w.y, w.z, w.w};
#pragma unroll
        for (int i = 0; i < 4; i++)
#pragma unroll
            for (int j = 0; j < 4; j++) acc2[i][j] = fmaf(av[i], wv[j], acc2[i][j]);
    }
#pragma unroll
    for (int i = 0; i < 4; i++) {
        const int n = n0 + ng * 4 + i;
        if (n < N_NODES) {
            const int b = b_s[ng * 4 + i];
#pragma unroll
            for (int j = 0; j < 4; j++) {
                const int c = cg * 4 + j;
                const float hn = acc2[i][j] + __ldg(bn2 + c) + a_s[c * 36 + ng * 4 + i];
                atomicAdd(&g_pool[b * 128 + c], hn);
            }
        }
    }
    if (t < 32 && n0 + t < N_NODES) atomicAdd(&g_cnt[b_s[t]], 1.0f);
}

__global__ void k_pool_final(float* __restrict__ out) {
    const int g = blockIdx.x;
    const int c = threadIdx.x;
    const float cnt = fmaxf(g_cnt[g], 1.0f);
    out[g * 128 + c] = g_pool[g * 128 + c] / cnt;
}

// ---------------- launcher ----------------
extern "C" void kernel_launch(void* const* d_in, const int* in_sizes, int n_in,
                              void* d_out, int out_size) {
    const float* h   = (const float*)d_in[0];
    const void*  ei  = d_in[1];
    const float* x   = (const float*)d_in[2];
    const float* ea  = (const float*)d_in[3];
    const void*  bat = d_in[4];
    const float* We1 = (const float*)d_in[5];
    const float* be1 = (const float*)d_in[6];
    const float* We2 = (const float*)d_in[7];
    const float* be2 = (const float*)d_in[8];
    const float* Wn1 = (const float*)d_in[9];
    const float* bn1 = (const float*)d_in[10];
    const float* Wn2 = (const float*)d_in[11];
    const float* bn2 = (const float*)d_in[12];
    float* out = (float*)d_out;

    cudaFuncSetAttribute(k_edge, cudaFuncAttributeMaxDynamicSharedMemorySize, EDGE_SMEM_BYTES);
    cudaFuncSetAttribute(k_node, cudaFuncAttributeMaxDynamicSharedMemorySize, NODE_SMEM_BYTES);

    k_init<<<(N_NODES * HID / 4 + 255) / 256, 256>>>(ei);                       // #1
    k_cvt_idx<<<(N_EDGES + 255) / 256, 256>>>(ei, bat);                         // #2
    k_node_pre<<<(N_NODES + NTILE - 1) / NTILE, 256>>>(h, We1, be1);            // #3
    k_edge<<<EGRID, 512, EDGE_SMEM_BYTES>>>(x, ea, We1, We2, be2);              // #4 (ncu slot)
    k_node<<<(N_NODES + NTILE - 1) / NTILE, 256, NODE_SMEM_BYTES>>>(h, Wn1, bn1, Wn2, bn2);
    k_pool_final<<<N_GRAPHS, HID>>>(out);
}

// round 10
// speedup vs baseline: 2.1031x; 1.4243x over previous
#include <cuda_runtime.h>
#include <cuda_bf16.h>
#include <cstdint>

#define N_NODES  50000
#define N_EDGES  800000
#define HID      128
#define EDGE_D   16
#define N_GRAPHS 64

#define ETILE 128
#define NTILE 32
#define NUM_ETILES (N_EDGES / ETILE)
#define NUM_PTILES ((N_NODES + 31) / 32)
#define EGRID 152

// ---------------- device scratch (static, no allocation) ----------------
__device__ float g_hAB[(size_t)N_NODES * 256];   // hA | hB  (51.2 MB)
__device__ float g_hn1[(size_t)N_NODES * 128];   // h @ Wn1a + bn1 (25.6 MB)
__device__ float g_agg[(size_t)N_NODES * HID];   // scatter target (25.6 MB)
__device__ float g_pool[N_GRAPHS * HID];         // sum of h per graph
__device__ float g_poolm[N_GRAPHS * HID];        // sum of mid per graph
__device__ float g_cnt[N_GRAPHS];
__device__ int   g_row[N_EDGES];
__device__ int   g_col[N_EDGES];
__device__ int   g_batch[N_NODES];
__device__ int   g_is64;

__device__ __forceinline__ float silu_f(float v) {
    return __fdividef(v, 1.0f + __expf(-v));
}

// bf16 mma m16n8k16: D += A(16x16) * B(16x8), A row-major, B col-major
__device__ __forceinline__ void mma_bf16(float* d, uint32_t a0, uint32_t a1,
                                         uint32_t a2, uint32_t a3,
                                         uint32_t b0, uint32_t b1) {
    asm volatile(
        "mma.sync.aligned.m16n8k16.row.col.f32.bf16.bf16.f32 "
        "{%0,%1,%2,%3}, {%4,%5,%6,%7}, {%8,%9}, {%0,%1,%2,%3};"
        : "+f"(d[0]), "+f"(d[1]), "+f"(d[2]), "+f"(d[3])
        : "r"(a0), "r"(a1), "r"(a2), "r"(a3), "r"(b0), "r"(b1));
}

__device__ __forceinline__ uint2 pack_hi4(float a, float b, float c, float d,
                                          float& ra, float& rb, float& rc, float& rd) {
    const __nv_bfloat16 ha = __float2bfloat16(a);
    const __nv_bfloat16 hb = __float2bfloat16(b);
    const __nv_bfloat16 hc = __float2bfloat16(c);
    const __nv_bfloat16 hd = __float2bfloat16(d);
    ra = a - __bfloat162float(ha);
    rb = b - __bfloat162float(hb);
    rc = c - __bfloat162float(hc);
    rd = d - __bfloat162float(hd);
    __nv_bfloat162 p0; p0.x = ha; p0.y = hb;
    __nv_bfloat162 p1; p1.x = hc; p1.y = hd;
    uint2 r;
    r.x = *reinterpret_cast<uint32_t*>(&p0);
    r.y = *reinterpret_cast<uint32_t*>(&p1);
    return r;
}
__device__ __forceinline__ uint2 pack_bf4(float a, float b, float c, float d) {
    __nv_bfloat162 p0; p0.x = __float2bfloat16(a); p0.y = __float2bfloat16(b);
    __nv_bfloat162 p1; p1.x = __float2bfloat16(c); p1.y = __float2bfloat16(d);
    uint2 r;
    r.x = *reinterpret_cast<uint32_t*>(&p0);
    r.y = *reinterpret_cast<uint32_t*>(&p1);
    return r;
}

// ---------------- init (launch #1) ----------------
__global__ void k_init(const void* __restrict__ ei) {
    const int i = blockIdx.x * blockDim.x + threadIdx.x;
    if (i < (N_NODES * HID) / 4)
        reinterpret_cast<float4*>(g_agg)[i] = make_float4(0.f, 0.f, 0.f, 0.f);
    if (i < N_GRAPHS * HID) { g_pool[i] = 0.f; g_poolm[i] = 0.f; }
    if (i < N_GRAPHS)       g_cnt[i] = 0.f;
    if (i == 0) {
        const unsigned int* p = (const unsigned int*)ei;
        int is64 = 1;
        for (int j = 0; j < 16; j++) if (p[2 * j + 1] != 0u) is64 = 0;
        g_is64 = is64;
    }
}

// ---------------- index conversion (launch #2) ----------------
__global__ void k_cvt_idx(const void* __restrict__ ei, const void* __restrict__ batch) {
    const int i = blockIdx.x * blockDim.x + threadIdx.x;
    const bool is64 = (g_is64 != 0);
    if (i < N_EDGES) {
        if (is64) {
            const long long* p = (const long long*)ei;
            g_row[i] = (int)p[i];
            g_col[i] = (int)p[N_EDGES + i];
        } else {
            const int* p = (const int*)ei;
            g_row[i] = p[i];
            g_col[i] = p[N_EDGES + i];
        }
    }
    if (i < N_NODES) {
        if (is64) g_batch[i] = (int)((const long long*)batch)[i];
        else      g_batch[i] = ((const int*)batch)[i];
    }
}

// ---------------- k_pre (launch #3): persistent mma pre-GEMM -------------------
// D[n][c] = h[n] @ [We1a | We1b | Wn1a][.,c] (+be1 on c<128, +bn1 on c>=256)
// N=384, K=128, 3-term bf16 split. 32-node tiles, warp tile m16 x n48.
#define BSTRIDE 136   // bf16 elements per row (272 B) -> conflict-free fragments

#define PB_BH   0                  // 384x136 bf16 hi = 104448 B
#define PB_BL   104448             // 104448 B
#define PB_AH   208896             // 32x136 bf16 hi = 8704 B
#define PB_AL   217600             // 8704 B
#define PB_BIAS 226304             // 384 f32 = 1536 B
#define PRE_SMEM_BYTES 227840

__global__ __launch_bounds__(512, 1) void k_pre(const float* __restrict__ h,
                                                const float* __restrict__ We1,
                                                const float* __restrict__ be1,
                                                const float* __restrict__ Wn1,
                                                const float* __restrict__ bn1) {
    extern __shared__ char smem[];
    __nv_bfloat16* Bh = reinterpret_cast<__nv_bfloat16*>(smem + PB_BH);
    __nv_bfloat16* Bl = reinterpret_cast<__nv_bfloat16*>(smem + PB_BL);
    __nv_bfloat16* Ah = reinterpret_cast<__nv_bfloat16*>(smem + PB_AH);
    __nv_bfloat16* Al = reinterpret_cast<__nv_bfloat16*>(smem + PB_AL);
    float* bias_s = reinterpret_cast<float*>(smem + PB_BIAS);

    const int t = threadIdx.x;
    const int w = t >> 5, lane = t & 31;

    // stage B = [We1a|We1b|Wn1a] as [c][k], split hi/lo (once per block)
    for (int i = t; i < 384 * 128; i += 512) {
        const int c = i >> 7, k = i & 127;
        float v;
        if (c < 128)       v = We1[k * 128 + c];
        else if (c < 256)  v = We1[(128 + k) * 128 + (c - 128)];
        else               v = Wn1[k * 128 + (c - 256)];
        const __nv_bfloat16 hi = __float2bfloat16(v);
        Bh[c * BSTRIDE + k] = hi;
        Bl[c * BSTRIDE + k] = __float2bfloat16(v - __bfloat162float(hi));
    }
    for (int i = t; i < 384; i += 512) {
        float b = 0.f;
        if (i < 128)      b = be1[i];
        else if (i >= 256) b = bn1[i - 256];
        bias_s[i] = b;
    }
    __syncthreads();

    const int mt = w & 1;        // 2 m-tiles of 16 nodes
    const int nb = w >> 1;       // 8 n-tiles of 48 cols
    const int g  = lane >> 2;    // 0..7
    const int tq = lane & 3;     // 0..3

    for (int tile = blockIdx.x; tile < NUM_PTILES; tile += EGRID) {
        const int n0 = tile * 32;
        __syncthreads();   // protect A buffers vs previous iteration readers
        // stage A (32 nodes x 128 k) hi/lo
        for (int idx = t; idx < 1024; idx += 512) {
            const int n = idx >> 5, kq = idx & 31;
            float4 v = make_float4(0.f, 0.f, 0.f, 0.f);
            if (n0 + n < N_NODES)
                v = *reinterpret_cast<const float4*>(h + (size_t)(n0 + n) * 128 + kq * 4);
            float la, lb, lc, ld;
            const uint2 hv = pack_hi4(v.x, v.y, v.z, v.w, la, lb, lc, ld);
            *reinterpret_cast<uint2*>(Ah + n * BSTRIDE + kq * 4) = hv;
            *reinterpret_cast<uint2*>(Al + n * BSTRIDE + kq * 4) = pack_bf4(la, lb, lc, ld);
        }
        __syncthreads();

        float d[6][4];
#pragma unroll
        for (int nt = 0; nt < 6; nt++)
#pragma unroll
            for (int j = 0; j < 4; j++) d[nt][j] = 0.f;

        const int arow = mt * 16 + g;
#pragma unroll
        for (int ks = 0; ks < 8; ks++) {
            const int kb = ks * 16;
            const __nv_bfloat16* Ap = Ah + arow * BSTRIDE + 2 * tq + kb;
            const uint32_t a0 = *reinterpret_cast<const uint32_t*>(Ap);
            const uint32_t a1 = *reinterpret_cast<const uint32_t*>(Ap + 8 * BSTRIDE);
            const uint32_t a2 = *reinterpret_cast<const uint32_t*>(Ap + 8);
            const uint32_t a3 = *reinterpret_cast<const uint32_t*>(Ap + 8 * BSTRIDE + 8);
            const __nv_bfloat16* Lp = Al + arow * BSTRIDE + 2 * tq + kb;
            const uint32_t l0 = *reinterpret_cast<const uint32_t*>(Lp);
            const uint32_t l1 = *reinterpret_cast<const uint32_t*>(Lp + 8 * BSTRIDE);
            const uint32_t l2 = *reinterpret_cast<const uint32_t*>(Lp + 8);
            const uint32_t l3 = *reinterpret_cast<const uint32_t*>(Lp + 8 * BSTRIDE + 8);
            uint32_t bf[6][2];
#pragma unroll
            for (int nt = 0; nt < 6; nt++) {
                const __nv_bfloat16* Bp = Bh + (nb * 48 + nt * 8 + g) * BSTRIDE + 2 * tq + kb;
                bf[nt][0] = *reinterpret_cast<const uint32_t*>(Bp);
                bf[nt][1] = *reinterpret_cast<const uint32_t*>(Bp + 8);
            }
#pragma unroll
            for (int nt = 0; nt < 6; nt++) {
                mma_bf16(d[nt], a0, a1, a2, a3, bf[nt][0], bf[nt][1]);
                mma_bf16(d[nt], l0, l1, l2, l3, bf[nt][0], bf[nt][1]);
            }
#pragma unroll
            for (int nt = 0; nt < 6; nt++) {
                const __nv_bfloat16* Bp = Bl + (nb * 48 + nt * 8 + g) * BSTRIDE + 2 * tq + kb;
                bf[nt][0] = *reinterpret_cast<const uint32_t*>(Bp);
                bf[nt][1] = *reinterpret_cast<const uint32_t*>(Bp + 8);
            }
#pragma unroll
            for (int nt = 0; nt < 6; nt++)
                mma_bf16(d[nt], a0, a1, a2, a3, bf[nt][0], bf[nt][1]);
        }

        // epilogue: +bias, write to g_hAB (c<256) or g_hn1 (c>=256)
        const int r0 = n0 + mt * 16 + g;
        const int r1 = r0 + 8;
#pragma unroll
        for (int nt = 0; nt < 6; nt++) {
            const int col = nb * 48 + nt * 8 + 2 * tq;
            const float b0 = bias_s[col], b1 = bias_s[col + 1];
            float2 v0 = make_float2(d[nt][0] + b0, d[nt][1] + b1);
            float2 v1 = make_float2(d[nt][2] + b0, d[nt][3] + b1);
            if (col < 256) {
                if (r0 < N_NODES) *reinterpret_cast<float2*>(g_hAB + (size_t)r0 * 256 + col) = v0;
                if (r1 < N_NODES) *reinterpret_cast<float2*>(g_hAB + (size_t)r1 * 256 + col) = v1;
            } else {
                if (r0 < N_NODES) *reinterpret_cast<float2*>(g_hn1 + (size_t)r0 * 128 + col - 256) = v0;
                if (r1 < N_NODES) *reinterpret_cast<float2*>(g_hn1 + (size_t)r1 * 128 + col - 256) = v1;
            }
        }
    }
}

// ---------------- fused edge kernel (launch #4; persistent, software-pipelined) ----------
#define SB_W2H   0
#define SB_W2L   34816
#define SB_U0H   69632
#define SB_U0L   104448
#define SB_U1H   139264
#define SB_U1L   174080
#define SB_W1E   208896
#define SB_W1R   217088
#define SB_BE2   217600
#define EDGE_SMEM_BYTES 218112

__device__ __forceinline__ void edge_phaseA(
    int e0, int w, int lane,
    const float* __restrict__ x, const float* __restrict__ ea,
    const float* W1e_s, float4 wr,
    __nv_bfloat16* uhi, __nv_bfloat16* ulo)
{
    const int ebase = w * 8;
    const int co    = lane * 4;
    int r8 = 0, c8 = 0;
    float rad8 = 0.f;
    if (lane < 8) {
        const int eg = e0 + ebase + lane;
        r8 = g_row[eg];
        c8 = g_col[eg];
        const float dx = x[r8 * 3 + 0] - x[c8 * 3 + 0];
        const float dy = x[r8 * 3 + 1] - x[c8 * 3 + 1];
        const float dz = x[r8 * 3 + 2] - x[c8 * 3 + 2];
        rad8 = dx * dx + dy * dy + dz * dz;
    }
    float acc[8][4];
#pragma unroll
    for (int ii = 0; ii < 8; ii++) {
        const int r   = __shfl_sync(0xffffffffu, r8, ii);
        const int c   = __shfl_sync(0xffffffffu, c8, ii);
        const float rad = __shfl_sync(0xffffffffu, rad8, ii);
        const float4 a4 = *reinterpret_cast<const float4*>(g_hAB + (size_t)r * 256 + co);
        const float4 b4 = *reinterpret_cast<const float4*>(g_hAB + (size_t)c * 256 + 128 + co);
        acc[ii][0] = fmaf(rad, wr.x, a4.x + b4.x);
        acc[ii][1] = fmaf(rad, wr.y, a4.y + b4.y);
        acc[ii][2] = fmaf(rad, wr.z, a4.z + b4.z);
        acc[ii][3] = fmaf(rad, wr.w, a4.w + b4.w);
    }
#pragma unroll
    for (int jb = 0; jb < 4; jb++) {
        float4 wv[4];
#pragma unroll
        for (int q = 0; q < 4; q++)
            wv[q] = *reinterpret_cast<const float4*>(W1e_s + (jb * 4 + q) * 128 + co);
#pragma unroll
        for (int ii = 0; ii < 8; ii++) {
            const float4 e4 = __ldg(reinterpret_cast<const float4*>(
                ea + (size_t)(e0 + ebase + ii) * 16 + jb * 4));
            const float ev[4] = {e4.x, e4.y, e4.z, e4.w};
#pragma unroll
            for (int q = 0; q < 4; q++) {
                acc[ii][0] = fmaf(ev[q], wv[q].x, acc[ii][0]);
                acc[ii][1] = fmaf(ev[q], wv[q].y, acc[ii][1]);
                acc[ii][2] = fmaf(ev[q], wv[q].z, acc[ii][2]);
                acc[ii][3] = fmaf(ev[q], wv[q].w, acc[ii][3]);
            }
        }
    }
#pragma unroll
    for (int ii = 0; ii < 8; ii++) {
        const int e = ebase + ii;
        const float sx = silu_f(acc[ii][0]), sy = silu_f(acc[ii][1]);
        const float sz = silu_f(acc[ii][2]), sw = silu_f(acc[ii][3]);
        float la, lb, lc, ld;
        const uint2 hv = pack_hi4(sx, sy, sz, sw, la, lb, lc, ld);
        *reinterpret_cast<uint2*>(uhi + e * BSTRIDE + co) = hv;
        *reinterpret_cast<uint2*>(ulo + e * BSTRIDE + co) = pack_bf4(la, lb, lc, ld);
    }
}

__device__ __forceinline__ void edge_phaseB(
    int e0, int mt2, int nq2, int g, int tq,
    const __nv_bfloat16* uhi, const __nv_bfloat16* ulo,
    const __nv_bfloat16* w2h, const __nv_bfloat16* w2l,
    const float* be2_s)
{
    float d[2][4][4];
#pragma unroll
    for (int mi = 0; mi < 2; mi++)
#pragma unroll
        for (int nt = 0; nt < 4; nt++)
#pragma unroll
            for (int j = 0; j < 4; j++) d[mi][nt][j] = 0.f;

    const int arow = mt2 * 32 + g;
    const int brow = nq2 * 32 + g;
#pragma unroll
    for (int ks = 0; ks < 8; ks++) {
        const int kb = ks * 16;
        uint32_t ah[2][4], al[2][4];
#pragma unroll
        for (int mi = 0; mi < 2; mi++) {
            const __nv_bfloat16* Ah = uhi + (arow + mi * 16) * BSTRIDE + 2 * tq + kb;
            ah[mi][0] = *reinterpret_cast<const uint32_t*>(Ah);
            ah[mi][1] = *reinterpret_cast<const uint32_t*>(Ah + 8 * BSTRIDE);
            ah[mi][2] = *reinterpret_cast<const uint32_t*>(Ah + 8);
            ah[mi][3] = *reinterpret_cast<const uint32_t*>(Ah + 8 * BSTRIDE + 8);
            const __nv_bfloat16* Al = ulo + (arow + mi * 16) * BSTRIDE + 2 * tq + kb;
            al[mi][0] = *reinterpret_cast<const uint32_t*>(Al);
            al[mi][1] = *reinterpret_cast<const uint32_t*>(Al + 8 * BSTRIDE);
            al[mi][2] = *reinterpret_cast<const uint32_t*>(Al + 8);
            al[mi][3] = *reinterpret_cast<const uint32_t*>(Al + 8 * BSTRIDE + 8);
        }
        uint32_t bf[4][2];
#pragma unroll
        for (int nt = 0; nt < 4; nt++) {
            const __nv_bfloat16* Bp = w2h + (brow + nt * 8) * BSTRIDE + 2 * tq + kb;
            bf[nt][0] = *reinterpret_cast<const uint32_t*>(Bp);
            bf[nt][1] = *reinterpret_cast<const uint32_t*>(Bp + 8);
        }
#pragma unroll
        for (int nt = 0; nt < 4; nt++)
#pragma unroll
            for (int mi = 0; mi < 2; mi++) {
                mma_bf16(d[mi][nt], ah[mi][0], ah[mi][1], ah[mi][2], ah[mi][3],
                         bf[nt][0], bf[nt][1]);
                mma_bf16(d[mi][nt], al[mi][0], al[mi][1], al[mi][2], al[mi][3],
                         bf[nt][0], bf[nt][1]);
            }
#pragma unroll
        for (int nt = 0; nt < 4; nt++) {
            const __nv_bfloat16* Bp = w2l + (brow + nt * 8) * BSTRIDE + 2 * tq + kb;
            bf[nt][0] = *reinterpret_cast<const uint32_t*>(Bp);
            bf[nt][1] = *reinterpret_cast<const uint32_t*>(Bp + 8);
        }
#pragma unroll
        for (int nt = 0; nt < 4; nt++)
#pragma unroll
            for (int mi = 0; mi < 2; mi++)
                mma_bf16(d[mi][nt], ah[mi][0], ah[mi][1], ah[mi][2], ah[mi][3],
                         bf[nt][0], bf[nt][1]);
    }

    const bool evenq = (tq & 1) == 0;
#pragma unroll
    for (int mi = 0; mi < 2; mi++) {
        const int er0 = g_row[e0 + mt2 * 32 + mi * 16 + g];
        const int er1 = g_row[e0 + mt2 * 32 + mi * 16 + g + 8];
#pragma unroll
        for (int nt = 0; nt < 4; nt++) {
            const int col = nq2 * 32 + nt * 8 + 2 * tq;
            const float b0v = be2_s[col];
            const float b1v = be2_s[col + 1];
            const float v00 = silu_f(d[mi][nt][0] + b0v);
            const float v01 = silu_f(d[mi][nt][1] + b1v);
            const float v10 = silu_f(d[mi][nt][2] + b0v);
            const float v11 = silu_f(d[mi][nt][3] + b1v);
            const float p00 = __shfl_xor_sync(0xffffffffu, v00, 1);
            const float p01 = __shfl_xor_sync(0xffffffffu, v01, 1);
            const float p10 = __shfl_xor_sync(0xffffffffu, v10, 1);
            const float p11 = __shfl_xor_sync(0xffffffffu, v11, 1);
            const int colbase = nq2 * 32 + nt * 8 + (tq & 2) * 2;
            if (evenq) {
                asm volatile("red.global.add.v4.f32 [%0], {%1, %2, %3, %4};"
                             :: "l"(g_agg + (size_t)er0 * 128 + colbase),
                                "f"(v00), "f"(v01), "f"(p00), "f"(p01) : "memory");
            } else {
                asm volatile("red.global.add.v4.f32 [%0], {%1, %2, %3, %4};"
                             :: "l"(g_agg + (size_t)er1 * 128 + colbase),
                                "f"(p10), "f"(p11), "f"(v10), "f"(v11) : "memory");
            }
        }
    }
}

__global__ __launch_bounds__(512, 1) void k_edge(const float* __restrict__ x,
                                                 const float* __restrict__ ea,
                                                 const float* __restrict__ We1,
                                                 const float* __restrict__ We2,
                                                 const float* __restrict__ be2) {
    extern __shared__ char smem[];
    __nv_bfloat16* w2h = reinterpret_cast<__nv_bfloat16*>(smem + SB_W2H);
    __nv_bfloat16* w2l = reinterpret_cast<__nv_bfloat16*>(smem + SB_W2L);
    __nv_bfloat16* ubh[2] = {reinterpret_cast<__nv_bfloat16*>(smem + SB_U0H),
                             reinterpret_cast<__nv_bfloat16*>(smem + SB_U1H)};
    __nv_bfloat16* ubl[2] = {reinterpret_cast<__nv_bfloat16*>(smem + SB_U0L),
                             reinterpret_cast<__nv_bfloat16*>(smem + SB_U1L)};
    float* W1e_s = reinterpret_cast<float*>(smem + SB_W1E);
    float* W1r_s = reinterpret_cast<float*>(smem + SB_W1R);
    float* be2_s = reinterpret_cast<float*>(smem + SB_BE2);

    const int t = threadIdx.x;
    const int w = t >> 5, lane = t & 31;

    for (int i = t; i < 16384; i += 512) {
        const int k = i >> 7, c = i & 127;
        const float v = We2[i];
        const __nv_bfloat16 hi = __float2bfloat16(v);
        w2h[c * BSTRIDE + k] = hi;
        w2l[c * BSTRIDE + k] = __float2bfloat16(v - __bfloat162float(hi));
    }
    for (int i = t; i < 2048; i += 512) W1e_s[i] = We1[257 * 128 + i];
    if (t < 128) {
        W1r_s[t] = We1[256 * 128 + t];
        be2_s[t] = be2[t];
    }
    __syncthreads();

    const float4 wr = *reinterpret_cast<const float4*>(W1r_s + lane * 4);

    const int mt2 = w & 3;
    const int nq2 = w >> 2;
    const int g   = lane >> 2;
    const int tq  = lane & 3;

    const int t0 = blockIdx.x;
    if (t0 < NUM_ETILES)
        edge_phaseA(t0 * ETILE, w, lane, x, ea, W1e_s, wr, ubh[0], ubl[0]);
    __syncthreads();

    int cur = 0;
    for (int tile = t0; tile < NUM_ETILES; tile += EGRID, cur ^= 1) {
        const int tn = tile + EGRID;
        if (tn < NUM_ETILES)
            edge_phaseA(tn * ETILE, w, lane, x, ea, W1e_s, wr, ubh[cur ^ 1], ubl[cur ^ 1]);
        edge_phaseB(tile * ETILE, mt2, nq2, g, tq, ubh[cur], ubl[cur], w2h, w2l, be2_s);
        __syncthreads();
    }
}

// ---------------- k_node (launch #5): mid = silu(hn1 + agg@Wn1b); scatter to pools ----
#define NODE_SMEM_FLOATS (128 * 36 + 32)
#define NODE_SMEM_BYTES  (NODE_SMEM_FLOATS * 4)

__global__ __launch_bounds__(256) void k_node(const float* __restrict__ h,
                                              const float* __restrict__ Wn1) {
    extern __shared__ float sm[];
    float* a_s = sm;                      // agg tile, k-major [k][n], 128 x 36
    int*   b_s = reinterpret_cast<int*>(sm + 128 * 36);

    const int n0 = blockIdx.x * NTILE;
    const int t = threadIdx.x;
    {
        const int n  = t >> 3;
        const int k4 = t & 7;
        const int ng = n0 + n;
#pragma unroll
        for (int j = 0; j < 4; j++) {
            const int k = k4 * 16 + j * 4;
            float4 w = make_float4(0.f, 0.f, 0.f, 0.f);
            if (ng < N_NODES)
                w = *reinterpret_cast<const float4*>(g_agg + (size_t)ng * 128 + k);
            a_s[(k + 0) * 36 + n] = w.x;
            a_s[(k + 1) * 36 + n] = w.y;
            a_s[(k + 2) * 36 + n] = w.z;
            a_s[(k + 3) * 36 + n] = w.w;
        }
        if (t < 32) b_s[t] = (n0 + t < N_NODES) ? g_batch[n0 + t] : 0;
    }
    __syncthreads();

    const int cg = t & 31;   // 32 col groups x 4 cols
    const int ng = t >> 5;   // 8 node groups x 4 nodes
    const int cn = cg * 4;
    float acc[4][4];
#pragma unroll
    for (int i = 0; i < 4; i++)
#pragma unroll
        for (int j = 0; j < 4; j++) acc[i][j] = 0.f;

    for (int k = 0; k < 128; k++) {
        float av[4];
#pragma unroll
        for (int i = 0; i < 4; i++) av[i] = a_s[k * 36 + ng * 4 + i];
        const float4 w = __ldg(reinterpret_cast<const float4*>(Wn1 + (128 + k) * 128 + cn));
        const float wv[4] = {w.x, w.y, w.z, w.w};
#pragma unroll
        for (int i = 0; i < 4; i++)
#pragma unroll
            for (int j = 0; j < 4; j++) acc[i][j] = fmaf(av[i], wv[j], acc[i][j]);
    }
#pragma unroll
    for (int i = 0; i < 4; i++) {
        const int n = n0 + ng * 4 + i;
        if (n < N_NODES) {
            const int b = b_s[ng * 4 + i];
            const float4 hn = *reinterpret_cast<const float4*>(g_hn1 + (size_t)n * 128 + cn);
            const float m0 = silu_f(acc[i][0] + hn.x);
            const float m1 = silu_f(acc[i][1] + hn.y);
            const float m2 = silu_f(acc[i][2] + hn.z);
            const float m3 = silu_f(acc[i][3] + hn.w);
            asm volatile("red.global.add.v4.f32 [%0], {%1, %2, %3, %4};"
                         :: "l"(g_poolm + b * 128 + cn), "f"(m0), "f"(m1), "f"(m2), "f"(m3)
                         : "memory");
            const float4 hv = *reinterpret_cast<const float4*>(h + (size_t)n * 128 + cn);
            asm volatile("red.global.add.v4.f32 [%0], {%1, %2, %3, %4};"
                         :: "l"(g_pool + b * 128 + cn), "f"(hv.x), "f"(hv.y), "f"(hv.z), "f"(hv.w)
                         : "memory");
        }
    }
    if (t < 32 && n0 + t < N_NODES) atomicAdd(&g_cnt[b_s[t]], 1.0f);
}

// ---------------- k_pool_final (launch #6): out = (pool_h + pool_mid@Wn2 + cnt*bn2)/cnt
__global__ void k_pool_final(const float* __restrict__ Wn2,
                             const float* __restrict__ bn2,
                             float* __restrict__ out) {
    __shared__ float pm[128];
    const int g = blockIdx.x;
    const int c = threadIdx.x;
    pm[c] = g_poolm[g * 128 + c];
    __syncthreads();
    float dot = 0.f;
    for (int k = 0; k < 128; k++)
        dot = fmaf(pm[k], __ldg(Wn2 + k * 128 + c), dot);
    const float cnt = g_cnt[g];
    const float s = g_pool[g * 128 + c] + dot + cnt * __ldg(bn2 + c);
    out[g * 128 + c] = s / fmaxf(cnt, 1.0f);
}

// ---------------- launcher ----------------
extern "C" void kernel_launch(void* const* d_in, const int* in_sizes, int n_in,
                              void* d_out, int out_size) {
    const float* h   = (const float*)d_in[0];
    const void*  ei  = d_in[1];
    const float* x   = (const float*)d_in[2];
    const float* ea  = (const float*)d_in[3];
    const void*  bat = d_in[4];
    const float* We1 = (const float*)d_in[5];
    const float* be1 = (const float*)d_in[6];
    const float* We2 = (const float*)d_in[7];
    const float* be2 = (const float*)d_in[8];
    const float* Wn1 = (const float*)d_in[9];
    const float* bn1 = (const float*)d_in[10];
    const float* Wn2 = (const float*)d_in[11];
    const float* bn2 = (const float*)d_in[12];
    float* out = (float*)d_out;

    cudaFuncSetAttribute(k_pre,  cudaFuncAttributeMaxDynamicSharedMemorySize, PRE_SMEM_BYTES);
    cudaFuncSetAttribute(k_edge, cudaFuncAttributeMaxDynamicSharedMemorySize, EDGE_SMEM_BYTES);
    cudaFuncSetAttribute(k_node, cudaFuncAttributeMaxDynamicSharedMemorySize, NODE_SMEM_BYTES);

    k_init<<<(N_NODES * HID / 4 + 255) / 256, 256>>>(ei);                       // #1
    k_cvt_idx<<<(N_EDGES + 255) / 256, 256>>>(ei, bat);                         // #2
    k_pre<<<EGRID, 512, PRE_SMEM_BYTES>>>(h, We1, be1, Wn1, bn1);               // #3
    k_edge<<<EGRID, 512, EDGE_SMEM_BYTES>>>(x, ea, We1, We2, be2);              // #4 (ncu slot)
    k_node<<<(N_NODES + NTILE - 1) / NTILE, 256, NODE_SMEM_BYTES>>>(h, Wn1);    // #5
    k_pool_final<<<N_GRAPHS, HID>>>(Wn2, bn2, out);                             // #6
}

// round 11
// speedup vs baseline: 2.2061x; 1.0490x over previous
#include <cuda_runtime.h>
#include <cuda_bf16.h>
#include <cstdint>

#define N_NODES  50000
#define N_EDGES  800000
#define HID      128
#define EDGE_D   16
#define N_GRAPHS 64

#define ETILE 128
#define NTILE 32
#define NUM_ETILES (N_EDGES / ETILE)
#define NUM_PTILES ((N_NODES + 31) / 32)
#define EGRID 152

// ---------------- device scratch (static, no allocation) ----------------
__device__ float g_hAB[(size_t)N_NODES * 256];   // hA | hB  (51.2 MB)
__device__ float g_hn1[(size_t)N_NODES * 128];   // h @ Wn1a + bn1 (25.6 MB)
__device__ float g_agg[(size_t)N_NODES * HID];   // scatter target (25.6 MB)
__device__ float g_pool[N_GRAPHS * HID];         // sum of h per graph
__device__ float g_poolm[N_GRAPHS * HID];        // sum of mid per graph
__device__ float g_cnt[N_GRAPHS];
__device__ int   g_row[N_EDGES];
__device__ int   g_col[N_EDGES];
__device__ int   g_batch[N_NODES];
__device__ int   g_is64;

__device__ __forceinline__ float silu_f(float v) {
    return __fdividef(v, 1.0f + __expf(-v));
}

// bf16 mma m16n8k16: D += A(16x16) * B(16x8), A row-major, B col-major
__device__ __forceinline__ void mma_bf16(float* d, uint32_t a0, uint32_t a1,
                                         uint32_t a2, uint32_t a3,
                                         uint32_t b0, uint32_t b1) {
    asm volatile(
        "mma.sync.aligned.m16n8k16.row.col.f32.bf16.bf16.f32 "
        "{%0,%1,%2,%3}, {%4,%5,%6,%7}, {%8,%9}, {%0,%1,%2,%3};"
        : "+f"(d[0]), "+f"(d[1]), "+f"(d[2]), "+f"(d[3])
        : "r"(a0), "r"(a1), "r"(a2), "r"(a3), "r"(b0), "r"(b1));
}

__device__ __forceinline__ void ldsm4(uint32_t* r, uint32_t addr) {
    asm volatile("ldmatrix.sync.aligned.m8n8.x4.shared.b16 {%0,%1,%2,%3}, [%4];"
                 : "=r"(r[0]), "=r"(r[1]), "=r"(r[2]), "=r"(r[3]) : "r"(addr));
}

__device__ __forceinline__ uint2 pack_hi4(float a, float b, float c, float d,
                                          float& ra, float& rb, float& rc, float& rd) {
    const __nv_bfloat16 ha = __float2bfloat16(a);
    const __nv_bfloat16 hb = __float2bfloat16(b);
    const __nv_bfloat16 hc = __float2bfloat16(c);
    const __nv_bfloat16 hd = __float2bfloat16(d);
    ra = a - __bfloat162float(ha);
    rb = b - __bfloat162float(hb);
    rc = c - __bfloat162float(hc);
    rd = d - __bfloat162float(hd);
    __nv_bfloat162 p0; p0.x = ha; p0.y = hb;
    __nv_bfloat162 p1; p1.x = hc; p1.y = hd;
    uint2 r;
    r.x = *reinterpret_cast<uint32_t*>(&p0);
    r.y = *reinterpret_cast<uint32_t*>(&p1);
    return r;
}
__device__ __forceinline__ uint2 pack_bf4(float a, float b, float c, float d) {
    __nv_bfloat162 p0; p0.x = __float2bfloat16(a); p0.y = __float2bfloat16(b);
    __nv_bfloat162 p1; p1.x = __float2bfloat16(c); p1.y = __float2bfloat16(d);
    uint2 r;
    r.x = *reinterpret_cast<uint32_t*>(&p0);
    r.y = *reinterpret_cast<uint32_t*>(&p1);
    return r;
}

// ---------------- init (launch #1) ----------------
__global__ void k_init(const void* __restrict__ ei) {
    const int i = blockIdx.x * blockDim.x + threadIdx.x;
    if (i < (N_NODES * HID) / 4)
        reinterpret_cast<float4*>(g_agg)[i] = make_float4(0.f, 0.f, 0.f, 0.f);
    if (i < N_GRAPHS * HID) { g_pool[i] = 0.f; g_poolm[i] = 0.f; }
    if (i < N_GRAPHS)       g_cnt[i] = 0.f;
    if (i == 0) {
        const unsigned int* p = (const unsigned int*)ei;
        int is64 = 1;
        for (int j = 0; j < 16; j++) if (p[2 * j + 1] != 0u) is64 = 0;
        g_is64 = is64;
    }
}

// ---------------- index conversion (launch #2) ----------------
__global__ void k_cvt_idx(const void* __restrict__ ei, const void* __restrict__ batch) {
    const int i = blockIdx.x * blockDim.x + threadIdx.x;
    const bool is64 = (g_is64 != 0);
    if (i < N_EDGES) {
        if (is64) {
            const long long* p = (const long long*)ei;
            g_row[i] = (int)p[i];
            g_col[i] = (int)p[N_EDGES + i];
        } else {
            const int* p = (const int*)ei;
            g_row[i] = p[i];
            g_col[i] = p[N_EDGES + i];
        }
    }
    if (i < N_NODES) {
        if (is64) g_batch[i] = (int)((const long long*)batch)[i];
        else      g_batch[i] = ((const int*)batch)[i];
    }
}

// ---------------- k_pre (launch #3): persistent mma pre-GEMM -------------------
#define BSTRIDE 136   // bf16 elements per row (272 B) -> conflict-free fragments

#define PB_BH   0                  // 384x136 bf16 hi = 104448 B
#define PB_BL   104448             // 104448 B
#define PB_AH   208896             // 32x136 bf16 hi = 8704 B
#define PB_AL   217600             // 8704 B
#define PB_BIAS 226304             // 384 f32 = 1536 B
#define PRE_SMEM_BYTES 227840

__global__ __launch_bounds__(512, 1) void k_pre(const float* __restrict__ h,
                                                const float* __restrict__ We1,
                                                const float* __restrict__ be1,
                                                const float* __restrict__ Wn1,
                                                const float* __restrict__ bn1) {
    extern __shared__ char smem[];
    __nv_bfloat16* Bh = reinterpret_cast<__nv_bfloat16*>(smem + PB_BH);
    __nv_bfloat16* Bl = reinterpret_cast<__nv_bfloat16*>(smem + PB_BL);
    __nv_bfloat16* Ah = reinterpret_cast<__nv_bfloat16*>(smem + PB_AH);
    __nv_bfloat16* Al = reinterpret_cast<__nv_bfloat16*>(smem + PB_AL);
    float* bias_s = reinterpret_cast<float*>(smem + PB_BIAS);

    const int t = threadIdx.x;
    const int w = t >> 5, lane = t & 31;

    for (int i = t; i < 384 * 128; i += 512) {
        const int c = i >> 7, k = i & 127;
        float v;
        if (c < 128)       v = We1[k * 128 + c];
        else if (c < 256)  v = We1[(128 + k) * 128 + (c - 128)];
        else               v = Wn1[k * 128 + (c - 256)];
        const __nv_bfloat16 hi = __float2bfloat16(v);
        Bh[c * BSTRIDE + k] = hi;
        Bl[c * BSTRIDE + k] = __float2bfloat16(v - __bfloat162float(hi));
    }
    for (int i = t; i < 384; i += 512) {
        float b = 0.f;
        if (i < 128)      b = be1[i];
        else if (i >= 256) b = bn1[i - 256];
        bias_s[i] = b;
    }
    __syncthreads();

    const int mt = w & 1;
    const int nb = w >> 1;
    const int g  = lane >> 2;
    const int tq = lane & 3;

    for (int tile = blockIdx.x; tile < NUM_PTILES; tile += EGRID) {
        const int n0 = tile * 32;
        __syncthreads();
        for (int idx = t; idx < 1024; idx += 512) {
            const int n = idx >> 5, kq = idx & 31;
            float4 v = make_float4(0.f, 0.f, 0.f, 0.f);
            if (n0 + n < N_NODES)
                v = *reinterpret_cast<const float4*>(h + (size_t)(n0 + n) * 128 + kq * 4);
            float la, lb, lc, ld;
            const uint2 hv = pack_hi4(v.x, v.y, v.z, v.w, la, lb, lc, ld);
            *reinterpret_cast<uint2*>(Ah + n * BSTRIDE + kq * 4) = hv;
            *reinterpret_cast<uint2*>(Al + n * BSTRIDE + kq * 4) = pack_bf4(la, lb, lc, ld);
        }
        __syncthreads();

        float d[6][4];
#pragma unroll
        for (int nt = 0; nt < 6; nt++)
#pragma unroll
            for (int j = 0; j < 4; j++) d[nt][j] = 0.f;

        const int arow = mt * 16 + g;
#pragma unroll
        for (int ks = 0; ks < 8; ks++) {
            const int kb = ks * 16;
            const __nv_bfloat16* Ap = Ah + arow * BSTRIDE + 2 * tq + kb;
            const uint32_t a0 = *reinterpret_cast<const uint32_t*>(Ap);
            const uint32_t a1 = *reinterpret_cast<const uint32_t*>(Ap + 8 * BSTRIDE);
            const uint32_t a2 = *reinterpret_cast<const uint32_t*>(Ap + 8);
            const uint32_t a3 = *reinterpret_cast<const uint32_t*>(Ap + 8 * BSTRIDE + 8);
            const __nv_bfloat16* Lp = Al + arow * BSTRIDE + 2 * tq + kb;
            const uint32_t l0 = *reinterpret_cast<const uint32_t*>(Lp);
            const uint32_t l1 = *reinterpret_cast<const uint32_t*>(Lp + 8 * BSTRIDE);
            const uint32_t l2 = *reinterpret_cast<const uint32_t*>(Lp + 8);
            const uint32_t l3 = *reinterpret_cast<const uint32_t*>(Lp + 8 * BSTRIDE + 8);
            uint32_t bf[6][2];
#pragma unroll
            for (int nt = 0; nt < 6; nt++) {
                const __nv_bfloat16* Bp = Bh + (nb * 48 + nt * 8 + g) * BSTRIDE + 2 * tq + kb;
                bf[nt][0] = *reinterpret_cast<const uint32_t*>(Bp);
                bf[nt][1] = *reinterpret_cast<const uint32_t*>(Bp + 8);
            }
#pragma unroll
            for (int nt = 0; nt < 6; nt++) {
                mma_bf16(d[nt], a0, a1, a2, a3, bf[nt][0], bf[nt][1]);
                mma_bf16(d[nt], l0, l1, l2, l3, bf[nt][0], bf[nt][1]);
            }
#pragma unroll
            for (int nt = 0; nt < 6; nt++) {
                const __nv_bfloat16* Bp = Bl + (nb * 48 + nt * 8 + g) * BSTRIDE + 2 * tq + kb;
                bf[nt][0] = *reinterpret_cast<const uint32_t*>(Bp);
                bf[nt][1] = *reinterpret_cast<const uint32_t*>(Bp + 8);
            }
#pragma unroll
            for (int nt = 0; nt < 6; nt++)
                mma_bf16(d[nt], a0, a1, a2, a3, bf[nt][0], bf[nt][1]);
        }

        const int r0 = n0 + mt * 16 + g;
        const int r1 = r0 + 8;
#pragma unroll
        for (int nt = 0; nt < 6; nt++) {
            const int col = nb * 48 + nt * 8 + 2 * tq;
            const float b0 = bias_s[col], b1 = bias_s[col + 1];
            float2 v0 = make_float2(d[nt][0] + b0, d[nt][1] + b1);
            float2 v1 = make_float2(d[nt][2] + b0, d[nt][3] + b1);
            if (col < 256) {
                if (r0 < N_NODES) *reinterpret_cast<float2*>(g_hAB + (size_t)r0 * 256 + col) = v0;
                if (r1 < N_NODES) *reinterpret_cast<float2*>(g_hAB + (size_t)r1 * 256 + col) = v1;
            } else {
                if (r0 < N_NODES) *reinterpret_cast<float2*>(g_hn1 + (size_t)r0 * 128 + col - 256) = v0;
                if (r1 < N_NODES) *reinterpret_cast<float2*>(g_hn1 + (size_t)r1 * 128 + col - 256) = v1;
            }
        }
    }
}

// ---------------- fused edge kernel (launch #4; persistent, pipelined, LDSM) ----------
#define SB_W2H   0
#define SB_W2L   34816
#define SB_U0H   69632
#define SB_U0L   104448
#define SB_U1H   139264
#define SB_U1L   174080
#define SB_W1E   208896
#define SB_W1R   217088
#define SB_BE2   217600
#define EDGE_SMEM_BYTES 218112

__device__ __forceinline__ void edge_phaseA(
    int e0, int w, int lane,
    const float* __restrict__ x, const float* __restrict__ ea,
    const float* W1e_s, float4 wr,
    __nv_bfloat16* uhi, __nv_bfloat16* ulo)
{
    const int ebase = w * 8;
    const int co    = lane * 4;
    int r8 = 0, c8 = 0;
    float rad8 = 0.f;
    if (lane < 8) {
        const int eg = e0 + ebase + lane;
        r8 = g_row[eg];
        c8 = g_col[eg];
        const float dx = x[r8 * 3 + 0] - x[c8 * 3 + 0];
        const float dy = x[r8 * 3 + 1] - x[c8 * 3 + 1];
        const float dz = x[r8 * 3 + 2] - x[c8 * 3 + 2];
        rad8 = dx * dx + dy * dy + dz * dz;
    }
    float acc[8][4];
#pragma unroll
    for (int ii = 0; ii < 8; ii++) {
        const int r   = __shfl_sync(0xffffffffu, r8, ii);
        const int c   = __shfl_sync(0xffffffffu, c8, ii);
        const float rad = __shfl_sync(0xffffffffu, rad8, ii);
        const float4 a4 = *reinterpret_cast<const float4*>(g_hAB + (size_t)r * 256 + co);
        const float4 b4 = *reinterpret_cast<const float4*>(g_hAB + (size_t)c * 256 + 128 + co);
        acc[ii][0] = fmaf(rad, wr.x, a4.x + b4.x);
        acc[ii][1] = fmaf(rad, wr.y, a4.y + b4.y);
        acc[ii][2] = fmaf(rad, wr.z, a4.z + b4.z);
        acc[ii][3] = fmaf(rad, wr.w, a4.w + b4.w);
    }
#pragma unroll
    for (int jb = 0; jb < 4; jb++) {
        float4 wv[4];
#pragma unroll
        for (int q = 0; q < 4; q++)
            wv[q] = *reinterpret_cast<const float4*>(W1e_s + (jb * 4 + q) * 128 + co);
#pragma unroll
        for (int ii = 0; ii < 8; ii++) {
            const float4 e4 = __ldg(reinterpret_cast<const float4*>(
                ea + (size_t)(e0 + ebase + ii) * 16 + jb * 4));
            const float ev[4] = {e4.x, e4.y, e4.z, e4.w};
#pragma unroll
            for (int q = 0; q < 4; q++) {
                acc[ii][0] = fmaf(ev[q], wv[q].x, acc[ii][0]);
                acc[ii][1] = fmaf(ev[q], wv[q].y, acc[ii][1]);
                acc[ii][2] = fmaf(ev[q], wv[q].z, acc[ii][2]);
                acc[ii][3] = fmaf(ev[q], wv[q].w, acc[ii][3]);
            }
        }
    }
#pragma unroll
    for (int ii = 0; ii < 8; ii++) {
        const int e = ebase + ii;
        const float sx = silu_f(acc[ii][0]), sy = silu_f(acc[ii][1]);
        const float sz = silu_f(acc[ii][2]), sw = silu_f(acc[ii][3]);
        float la, lb, lc, ld;
        const uint2 hv = pack_hi4(sx, sy, sz, sw, la, lb, lc, ld);
        *reinterpret_cast<uint2*>(uhi + e * BSTRIDE + co) = hv;
        *reinterpret_cast<uint2*>(ulo + e * BSTRIDE + co) = pack_bf4(la, lb, lc, ld);
    }
}

// Phase B with ldmatrix fragment loads.
// A-x4 lane map:  row = base + (lane&15), koff = (lane&16)?8:0  -> {a0,a1,a2,a3}
// B-x4 lane map:  row = base + ((lane>>4)&1)*8 + (lane&7), koff = (lane&8)?8:0
//                 -> {b0,b1 of nt=2p, b0,b1 of nt=2p+1}
__device__ __forceinline__ void edge_phaseB(
    int e0, int mt2, int nq2, int lane, int g, int tq,
    const __nv_bfloat16* uhi, const __nv_bfloat16* ulo,
    const __nv_bfloat16* w2h, const __nv_bfloat16* w2l,
    const float* be2_s)
{
    float d[2][4][4];
#pragma unroll
    for (int mi = 0; mi < 2; mi++)
#pragma unroll
        for (int nt = 0; nt < 4; nt++)
#pragma unroll
            for (int j = 0; j < 4; j++) d[mi][nt][j] = 0.f;

    const int rA   = lane & 15;
    const int kA   = (lane & 16) ? 8 : 0;
    const int rB   = ((lane >> 4) & 1) * 8 + (lane & 7);
    const int kB   = (lane & 8) ? 8 : 0;

    const uint32_t uhi_s = (uint32_t)__cvta_generic_to_shared(uhi);
    const uint32_t ulo_s = (uint32_t)__cvta_generic_to_shared(ulo);
    const uint32_t w2h_s = (uint32_t)__cvta_generic_to_shared(w2h);
    const uint32_t w2l_s = (uint32_t)__cvta_generic_to_shared(w2l);

    const uint32_t aoff = (uint32_t)(((mt2 * 32 + rA) * BSTRIDE + kA) * 2);
    const uint32_t boff = (uint32_t)(((nq2 * 32 + rB) * BSTRIDE + kB) * 2);
    const uint32_t mstep = 16 * BSTRIDE * 2;   // 16 rows

#pragma unroll
    for (int ks = 0; ks < 8; ks++) {
        const uint32_t kb2 = ks * 32;          // 16 bf16 = 32 bytes
        uint32_t ah[2][4], al[2][4], bh[2][4], bl[2][4];
        ldsm4(ah[0], uhi_s + aoff + kb2);
        ldsm4(ah[1], uhi_s + aoff + mstep + kb2);
        ldsm4(al[0], ulo_s + aoff + kb2);
        ldsm4(al[1], ulo_s + aoff + mstep + kb2);
        ldsm4(bh[0], w2h_s + boff + kb2);
        ldsm4(bh[1], w2h_s + boff + mstep + kb2);
        ldsm4(bl[0], w2l_s + boff + kb2);
        ldsm4(bl[1], w2l_s + boff + mstep + kb2);
#pragma unroll
        for (int p = 0; p < 2; p++)
#pragma unroll
            for (int sub = 0; sub < 2; sub++) {
                const int nt = p * 2 + sub;
                const uint32_t b0 = bh[p][sub * 2], b1 = bh[p][sub * 2 + 1];
#pragma unroll
                for (int mi = 0; mi < 2; mi++) {
                    mma_bf16(d[mi][nt], ah[mi][0], ah[mi][1], ah[mi][2], ah[mi][3], b0, b1);
                    mma_bf16(d[mi][nt], al[mi][0], al[mi][1], al[mi][2], al[mi][3], b0, b1);
                }
            }
#pragma unroll
        for (int p = 0; p < 2; p++)
#pragma unroll
            for (int sub = 0; sub < 2; sub++) {
                const int nt = p * 2 + sub;
                const uint32_t b0 = bl[p][sub * 2], b1 = bl[p][sub * 2 + 1];
#pragma unroll
                for (int mi = 0; mi < 2; mi++)
                    mma_bf16(d[mi][nt], ah[mi][0], ah[mi][1], ah[mi][2], ah[mi][3], b0, b1);
            }
    }

    const bool evenq = (tq & 1) == 0;
#pragma unroll
    for (int mi = 0; mi < 2; mi++) {
        const int er0 = g_row[e0 + mt2 * 32 + mi * 16 + g];
        const int er1 = g_row[e0 + mt2 * 32 + mi * 16 + g + 8];
#pragma unroll
        for (int nt = 0; nt < 4; nt++) {
            const int col = nq2 * 32 + nt * 8 + 2 * tq;
            const float b0v = be2_s[col];
            const float b1v = be2_s[col + 1];
            const float v00 = silu_f(d[mi][nt][0] + b0v);
            const float v01 = silu_f(d[mi][nt][1] + b1v);
            const float v10 = silu_f(d[mi][nt][2] + b0v);
            const float v11 = silu_f(d[mi][nt][3] + b1v);
            const float p00 = __shfl_xor_sync(0xffffffffu, v00, 1);
            const float p01 = __shfl_xor_sync(0xffffffffu, v01, 1);
            const float p10 = __shfl_xor_sync(0xffffffffu, v10, 1);
            const float p11 = __shfl_xor_sync(0xffffffffu, v11, 1);
            const int colbase = nq2 * 32 + nt * 8 + (tq & 2) * 2;
            if (evenq) {
                asm volatile("red.global.add.v4.f32 [%0], {%1, %2, %3, %4};"
                             :: "l"(g_agg + (size_t)er0 * 128 + colbase),
                                "f"(v00), "f"(v01), "f"(p00), "f"(p01) : "memory");
            } else {
                asm volatile("red.global.add.v4.f32 [%0], {%1, %2, %3, %4};"
                             :: "l"(g_agg + (size_t)er1 * 128 + colbase),
                                "f"(p10), "f"(p11), "f"(v10), "f"(v11) : "memory");
            }
        }
    }
}

__global__ __launch_bounds__(512, 1) void k_edge(const float* __restrict__ x,
                                                 const float* __restrict__ ea,
                                                 const float* __restrict__ We1,
                                                 const float* __restrict__ We2,
                                                 const float* __restrict__ be2) {
    extern __shared__ char smem[];
    __nv_bfloat16* w2h = reinterpret_cast<__nv_bfloat16*>(smem + SB_W2H);
    __nv_bfloat16* w2l = reinterpret_cast<__nv_bfloat16*>(smem + SB_W2L);
    __nv_bfloat16* ubh[2] = {reinterpret_cast<__nv_bfloat16*>(smem + SB_U0H),
                             reinterpret_cast<__nv_bfloat16*>(smem + SB_U1H)};
    __nv_bfloat16* ubl[2] = {reinterpret_cast<__nv_bfloat16*>(smem + SB_U0L),
                             reinterpret_cast<__nv_bfloat16*>(smem + SB_U1L)};
    float* W1e_s = reinterpret_cast<float*>(smem + SB_W1E);
    float* W1r_s = reinterpret_cast<float*>(smem + SB_W1R);
    float* be2_s = reinterpret_cast<float*>(smem + SB_BE2);

    const int t = threadIdx.x;
    const int w = t >> 5, lane = t & 31;

    for (int i = t; i < 16384; i += 512) {
        const int k = i >> 7, c = i & 127;
        const float v = We2[i];
        const __nv_bfloat16 hi = __float2bfloat16(v);
        w2h[c * BSTRIDE + k] = hi;
        w2l[c * BSTRIDE + k] = __float2bfloat16(v - __bfloat162float(hi));
    }
    for (int i = t; i < 2048; i += 512) W1e_s[i] = We1[257 * 128 + i];
    if (t < 128) {
        W1r_s[t] = We1[256 * 128 + t];
        be2_s[t] = be2[t];
    }
    __syncthreads();

    const float4 wr = *reinterpret_cast<const float4*>(W1r_s + lane * 4);

    const int mt2 = w & 3;
    const int nq2 = w >> 2;
    const int g   = lane >> 2;
    const int tq  = lane & 3;

    const int t0 = blockIdx.x;
    if (t0 < NUM_ETILES)
        edge_phaseA(t0 * ETILE, w, lane, x, ea, W1e_s, wr, ubh[0], ubl[0]);
    __syncthreads();

    int cur = 0;
    for (int tile = t0; tile < NUM_ETILES; tile += EGRID, cur ^= 1) {
        const int tn = tile + EGRID;
        if (tn < NUM_ETILES)
            edge_phaseA(tn * ETILE, w, lane, x, ea, W1e_s, wr, ubh[cur ^ 1], ubl[cur ^ 1]);
        edge_phaseB(tile * ETILE, mt2, nq2, lane, g, tq, ubh[cur], ubl[cur], w2h, w2l, be2_s);
        __syncthreads();
    }
}

// ---------------- k_node (launch #5): mid = silu(hn1 + agg@Wn1b); scatter to pools ----
#define NODE_SMEM_FLOATS (128 * 36 + 32)
#define NODE_SMEM_BYTES  (NODE_SMEM_FLOATS * 4)

__global__ __launch_bounds__(256) void k_node(const float* __restrict__ h,
                                              const float* __restrict__ Wn1) {
    extern __shared__ float sm[];
    float* a_s = sm;
    int*   b_s = reinterpret_cast<int*>(sm + 128 * 36);

    const int n0 = blockIdx.x * NTILE;
    const int t = threadIdx.x;
    {
        const int n  = t >> 3;
        const int k4 = t & 7;
        const int ng = n0 + n;
#pragma unroll
        for (int j = 0; j < 4; j++) {
            const int k = k4 * 16 + j * 4;
            float4 w = make_float4(0.f, 0.f, 0.f, 0.f);
            if (ng < N_NODES)
                w = *reinterpret_cast<const float4*>(g_agg + (size_t)ng * 128 + k);
            a_s[(k + 0) * 36 + n] = w.x;
            a_s[(k + 1) * 36 + n] = w.y;
            a_s[(k + 2) * 36 + n] = w.z;
            a_s[(k + 3) * 36 + n] = w.w;
        }
        if (t < 32) b_s[t] = (n0 + t < N_NODES) ? g_batch[n0 + t] : 0;
    }
    __syncthreads();

    const int cg = t & 31;
    const int ng = t >> 5;
    const int cn = cg * 4;
    float acc[4][4];
#pragma unroll
    for (int i = 0; i < 4; i++)
#pragma unroll
        for (int j = 0; j < 4; j++) acc[i][j] = 0.f;

    for (int k = 0; k < 128; k++) {
        float av[4];
#pragma unroll
        for (int i = 0; i < 4; i++) av[i] = a_s[k * 36 + ng * 4 + i];
        const float4 w = __ldg(reinterpret_cast<const float4*>(Wn1 + (128 + k) * 128 + cn));
        const float wv[4] = {w.x, w.y, w.z, w.w};
#pragma unroll
        for (int i = 0; i < 4; i++)
#pragma unroll
            for (int j = 0; j < 4; j++) acc[i][j] = fmaf(av[i], wv[j], acc[i][j]);
    }
#pragma unroll
    for (int i = 0; i < 4; i++) {
        const int n = n0 + ng * 4 + i;
        if (n < N_NODES) {
            const int b = b_s[ng * 4 + i];
            const float4 hn = *reinterpret_cast<const float4*>(g_hn1 + (size_t)n * 128 + cn);
            const float m0 = silu_f(acc[i][0] + hn.x);
            const float m1 = silu_f(acc[i][1] + hn.y);
            const float m2 = silu_f(acc[i][2] + hn.z);
            const float m3 = silu_f(acc[i][3] + hn.w);
            asm volatile("red.global.add.v4.f32 [%0], {%1, %2, %3, %4};"
                         :: "l"(g_poolm + b * 128 + cn), "f"(m0), "f"(m1), "f"(m2), "f"(m3)
                         : "memory");
            const float4 hv = *reinterpret_cast<const float4*>(h + (size_t)n * 128 + cn);
            asm volatile("red.global.add.v4.f32 [%0], {%1, %2, %3, %4};"
                         :: "l"(g_pool + b * 128 + cn), "f"(hv.x), "f"(hv.y), "f"(hv.z), "f"(hv.w)
                         : "memory");
        }
    }
    if (t < 32 && n0 + t < N_NODES) atomicAdd(&g_cnt[b_s[t]], 1.0f);
}

// ---------------- k_pool_final (launch #6) ----------------
__global__ void k_pool_final(const float* __restrict__ Wn2,
                             const float* __restrict__ bn2,
                             float* __restrict__ out) {
    __shared__ float pm[128];
    const int g = blockIdx.x;
    const int c = threadIdx.x;
    pm[c] = g_poolm[g * 128 + c];
    __syncthreads();
    float dot = 0.f;
    for (int k = 0; k < 128; k++)
        dot = fmaf(pm[k], __ldg(Wn2 + k * 128 + c), dot);
    const float cnt = g_cnt[g];
    const float s = g_pool[g * 128 + c] + dot + cnt * __ldg(bn2 + c);
    out[g * 128 + c] = s / fmaxf(cnt, 1.0f);
}

// ---------------- launcher ----------------
extern "C" void kernel_launch(void* const* d_in, const int* in_sizes, int n_in,
                              void* d_out, int out_size) {
    const float* h   = (const float*)d_in[0];
    const void*  ei  = d_in[1];
    const float* x   = (const float*)d_in[2];
    const float* ea  = (const float*)d_in[3];
    const void*  bat = d_in[4];
    const float* We1 = (const float*)d_in[5];
    const float* be1 = (const float*)d_in[6];
    const float* We2 = (const float*)d_in[7];
    const float* be2 = (const float*)d_in[8];
    const float* Wn1 = (const float*)d_in[9];
    const float* bn1 = (const float*)d_in[10];
    const float* Wn2 = (const float*)d_in[11];
    const float* bn2 = (const float*)d_in[12];
    float* out = (float*)d_out;

    cudaFuncSetAttribute(k_pre,  cudaFuncAttributeMaxDynamicSharedMemorySize, PRE_SMEM_BYTES);
    cudaFuncSetAttribute(k_edge, cudaFuncAttributeMaxDynamicSharedMemorySize, EDGE_SMEM_BYTES);
    cudaFuncSetAttribute(k_node, cudaFuncAttributeMaxDynamicSharedMemorySize, NODE_SMEM_BYTES);

    k_init<<<(N_NODES * HID / 4 + 255) / 256, 256>>>(ei);                       // #1
    k_cvt_idx<<<(N_EDGES + 255) / 256, 256>>>(ei, bat);                         // #2
    k_pre<<<EGRID, 512, PRE_SMEM_BYTES>>>(h, We1, be1, Wn1, bn1);               // #3
    k_edge<<<EGRID, 512, EDGE_SMEM_BYTES>>>(x, ea, We1, We2, be2);              // #4 (ncu slot)
    k_node<<<(N_NODES + NTILE - 1) / NTILE, 256, NODE_SMEM_BYTES>>>(h, Wn1);    // #5
    k_pool_final<<<N_GRAPHS, HID>>>(Wn2, bn2, out);                             // #6
}

// round 12
// speedup vs baseline: 2.2409x; 1.0158x over previous
#include <cuda_runtime.h>
#include <cuda_bf16.h>
#include <cstdint>

#define N_NODES  50000
#define N_EDGES  800000
#define HID      128
#define EDGE_D   16
#define N_GRAPHS 64

#define ETILE 64
#define NTILE 32
#define NUM_ETILES (N_EDGES / ETILE)
#define NUM_PTILES ((N_NODES + 31) / 32)
#define EGRID 304
#define PGRID 152

// ---------------- device scratch (static, no allocation) ----------------
__device__ float g_hAB[(size_t)N_NODES * 256];   // hA | hB  (51.2 MB)
__device__ float g_hn1[(size_t)N_NODES * 128];   // h @ Wn1a + bn1 (25.6 MB)
__device__ float g_agg[(size_t)N_NODES * HID];   // scatter target (25.6 MB)
__device__ float g_pool[N_GRAPHS * HID];         // sum of h per graph
__device__ float g_poolm[N_GRAPHS * HID];        // sum of mid per graph
__device__ float g_cnt[N_GRAPHS];
__device__ int   g_row[N_EDGES];
__device__ int   g_col[N_EDGES];
__device__ int   g_batch[N_NODES];
__device__ int   g_is64;

__device__ __forceinline__ float silu_f(float v) {
    return __fdividef(v, 1.0f + __expf(-v));
}

// bf16 mma m16n8k16: D += A(16x16) * B(16x8), A row-major, B col-major
__device__ __forceinline__ void mma_bf16(float* d, uint32_t a0, uint32_t a1,
                                         uint32_t a2, uint32_t a3,
                                         uint32_t b0, uint32_t b1) {
    asm volatile(
        "mma.sync.aligned.m16n8k16.row.col.f32.bf16.bf16.f32 "
        "{%0,%1,%2,%3}, {%4,%5,%6,%7}, {%8,%9}, {%0,%1,%2,%3};"
        : "+f"(d[0]), "+f"(d[1]), "+f"(d[2]), "+f"(d[3])
        : "r"(a0), "r"(a1), "r"(a2), "r"(a3), "r"(b0), "r"(b1));
}

__device__ __forceinline__ void ldsm4(uint32_t* r, uint32_t addr) {
    asm volatile("ldmatrix.sync.aligned.m8n8.x4.shared.b16 {%0,%1,%2,%3}, [%4];"
                 : "=r"(r[0]), "=r"(r[1]), "=r"(r[2]), "=r"(r[3]) : "r"(addr));
}

__device__ __forceinline__ uint2 pack_hi4(float a, float b, float c, float d,
                                          float& ra, float& rb, float& rc, float& rd) {
    const __nv_bfloat16 ha = __float2bfloat16(a);
    const __nv_bfloat16 hb = __float2bfloat16(b);
    const __nv_bfloat16 hc = __float2bfloat16(c);
    const __nv_bfloat16 hd = __float2bfloat16(d);
    ra = a - __bfloat162float(ha);
    rb = b - __bfloat162float(hb);
    rc = c - __bfloat162float(hc);
    rd = d - __bfloat162float(hd);
    __nv_bfloat162 p0; p0.x = ha; p0.y = hb;
    __nv_bfloat162 p1; p1.x = hc; p1.y = hd;
    uint2 r;
    r.x = *reinterpret_cast<uint32_t*>(&p0);
    r.y = *reinterpret_cast<uint32_t*>(&p1);
    return r;
}
__device__ __forceinline__ uint2 pack_bf4(float a, float b, float c, float d) {
    __nv_bfloat162 p0; p0.x = __float2bfloat16(a); p0.y = __float2bfloat16(b);
    __nv_bfloat162 p1; p1.x = __float2bfloat16(c); p1.y = __float2bfloat16(d);
    uint2 r;
    r.x = *reinterpret_cast<uint32_t*>(&p0);
    r.y = *reinterpret_cast<uint32_t*>(&p1);
    return r;
}

// ---------------- init (launch #1) ----------------
__global__ void k_init(const void* __restrict__ ei) {
    const int i = blockIdx.x * blockDim.x + threadIdx.x;
    if (i < (N_NODES * HID) / 4)
        reinterpret_cast<float4*>(g_agg)[i] = make_float4(0.f, 0.f, 0.f, 0.f);
    if (i < N_GRAPHS * HID) { g_pool[i] = 0.f; g_poolm[i] = 0.f; }
    if (i < N_GRAPHS)       g_cnt[i] = 0.f;
    if (i == 0) {
        const unsigned int* p = (const unsigned int*)ei;
        int is64 = 1;
        for (int j = 0; j < 16; j++) if (p[2 * j + 1] != 0u) is64 = 0;
        g_is64 = is64;
    }
}

// ---------------- index conversion (launch #2) ----------------
__global__ void k_cvt_idx(const void* __restrict__ ei, const void* __restrict__ batch) {
    const int i = blockIdx.x * blockDim.x + threadIdx.x;
    const bool is64 = (g_is64 != 0);
    if (i < N_EDGES) {
        if (is64) {
            const long long* p = (const long long*)ei;
            g_row[i] = (int)p[i];
            g_col[i] = (int)p[N_EDGES + i];
        } else {
            const int* p = (const int*)ei;
            g_row[i] = p[i];
            g_col[i] = p[N_EDGES + i];
        }
    }
    if (i < N_NODES) {
        if (is64) g_batch[i] = (int)((const long long*)batch)[i];
        else      g_batch[i] = ((const int*)batch)[i];
    }
}

// ---------------- k_pre (launch #3): persistent mma pre-GEMM -------------------
#define BSTRIDE 136   // bf16 elements per row (272 B) -> conflict-free fragments

#define PB_BH   0                  // 384x136 bf16 hi = 104448 B
#define PB_BL   104448             // 104448 B
#define PB_AH   208896             // 32x136 bf16 hi = 8704 B
#define PB_AL   217600             // 8704 B
#define PB_BIAS 226304             // 384 f32 = 1536 B
#define PRE_SMEM_BYTES 227840

__global__ __launch_bounds__(512, 1) void k_pre(const float* __restrict__ h,
                                                const float* __restrict__ We1,
                                                const float* __restrict__ be1,
                                                const float* __restrict__ Wn1,
                                                const float* __restrict__ bn1) {
    extern __shared__ char smem[];
    __nv_bfloat16* Bh = reinterpret_cast<__nv_bfloat16*>(smem + PB_BH);
    __nv_bfloat16* Bl = reinterpret_cast<__nv_bfloat16*>(smem + PB_BL);
    __nv_bfloat16* Ah = reinterpret_cast<__nv_bfloat16*>(smem + PB_AH);
    __nv_bfloat16* Al = reinterpret_cast<__nv_bfloat16*>(smem + PB_AL);
    float* bias_s = reinterpret_cast<float*>(smem + PB_BIAS);

    const int t = threadIdx.x;
    const int w = t >> 5, lane = t & 31;

    for (int i = t; i < 384 * 128; i += 512) {
        const int c = i >> 7, k = i & 127;
        float v;
        if (c < 128)       v = We1[k * 128 + c];
        else if (c < 256)  v = We1[(128 + k) * 128 + (c - 128)];
        else               v = Wn1[k * 128 + (c - 256)];
        const __nv_bfloat16 hi = __float2bfloat16(v);
        Bh[c * BSTRIDE + k] = hi;
        Bl[c * BSTRIDE + k] = __float2bfloat16(v - __bfloat162float(hi));
    }
    for (int i = t; i < 384; i += 512) {
        float b = 0.f;
        if (i < 128)      b = be1[i];
        else if (i >= 256) b = bn1[i - 256];
        bias_s[i] = b;
    }
    __syncthreads();

    const int mt = w & 1;
    const int nb = w >> 1;
    const int g  = lane >> 2;
    const int tq = lane & 3;

    for (int tile = blockIdx.x; tile < NUM_PTILES; tile += PGRID) {
        const int n0 = tile * 32;
        __syncthreads();
        for (int idx = t; idx < 1024; idx += 512) {
            const int n = idx >> 5, kq = idx & 31;
            float4 v = make_float4(0.f, 0.f, 0.f, 0.f);
            if (n0 + n < N_NODES)
                v = *reinterpret_cast<const float4*>(h + (size_t)(n0 + n) * 128 + kq * 4);
            float la, lb, lc, ld;
            const uint2 hv = pack_hi4(v.x, v.y, v.z, v.w, la, lb, lc, ld);
            *reinterpret_cast<uint2*>(Ah + n * BSTRIDE + kq * 4) = hv;
            *reinterpret_cast<uint2*>(Al + n * BSTRIDE + kq * 4) = pack_bf4(la, lb, lc, ld);
        }
        __syncthreads();

        float d[6][4];
#pragma unroll
        for (int nt = 0; nt < 6; nt++)
#pragma unroll
            for (int j = 0; j < 4; j++) d[nt][j] = 0.f;

        const int arow = mt * 16 + g;
#pragma unroll
        for (int ks = 0; ks < 8; ks++) {
            const int kb = ks * 16;
            const __nv_bfloat16* Ap = Ah + arow * BSTRIDE + 2 * tq + kb;
            const uint32_t a0 = *reinterpret_cast<const uint32_t*>(Ap);
            const uint32_t a1 = *reinterpret_cast<const uint32_t*>(Ap + 8 * BSTRIDE);
            const uint32_t a2 = *reinterpret_cast<const uint32_t*>(Ap + 8);
            const uint32_t a3 = *reinterpret_cast<const uint32_t*>(Ap + 8 * BSTRIDE + 8);
            const __nv_bfloat16* Lp = Al + arow * BSTRIDE + 2 * tq + kb;
            const uint32_t l0 = *reinterpret_cast<const uint32_t*>(Lp);
            const uint32_t l1 = *reinterpret_cast<const uint32_t*>(Lp + 8 * BSTRIDE);
            const uint32_t l2 = *reinterpret_cast<const uint32_t*>(Lp + 8);
            const uint32_t l3 = *reinterpret_cast<const uint32_t*>(Lp + 8 * BSTRIDE + 8);
            uint32_t bf[6][2];
#pragma unroll
            for (int nt = 0; nt < 6; nt++) {
                const __nv_bfloat16* Bp = Bh + (nb * 48 + nt * 8 + g) * BSTRIDE + 2 * tq + kb;
                bf[nt][0] = *reinterpret_cast<const uint32_t*>(Bp);
                bf[nt][1] = *reinterpret_cast<const uint32_t*>(Bp + 8);
            }
#pragma unroll
            for (int nt = 0; nt < 6; nt++) {
                mma_bf16(d[nt], a0, a1, a2, a3, bf[nt][0], bf[nt][1]);
                mma_bf16(d[nt], l0, l1, l2, l3, bf[nt][0], bf[nt][1]);
            }
#pragma unroll
            for (int nt = 0; nt < 6; nt++) {
                const __nv_bfloat16* Bp = Bl + (nb * 48 + nt * 8 + g) * BSTRIDE + 2 * tq + kb;
                bf[nt][0] = *reinterpret_cast<const uint32_t*>(Bp);
                bf[nt][1] = *reinterpret_cast<const uint32_t*>(Bp + 8);
            }
#pragma unroll
            for (int nt = 0; nt < 6; nt++)
                mma_bf16(d[nt], a0, a1, a2, a3, bf[nt][0], bf[nt][1]);
        }

        const int r0 = n0 + mt * 16 + g;
        const int r1 = r0 + 8;
#pragma unroll
        for (int nt = 0; nt < 6; nt++) {
            const int col = nb * 48 + nt * 8 + 2 * tq;
            const float b0 = bias_s[col], b1 = bias_s[col + 1];
            float2 v0 = make_float2(d[nt][0] + b0, d[nt][1] + b1);
            float2 v1 = make_float2(d[nt][2] + b0, d[nt][3] + b1);
            if (col < 256) {
                if (r0 < N_NODES) *reinterpret_cast<float2*>(g_hAB + (size_t)r0 * 256 + col) = v0;
                if (r1 < N_NODES) *reinterpret_cast<float2*>(g_hAB + (size_t)r1 * 256 + col) = v1;
            } else {
                if (r0 < N_NODES) *reinterpret_cast<float2*>(g_hn1 + (size_t)r0 * 128 + col - 256) = v0;
                if (r1 < N_NODES) *reinterpret_cast<float2*>(g_hn1 + (size_t)r1 * 128 + col - 256) = v1;
            }
        }
    }
}

// ---------------- fused edge kernel (launch #4; 2 CTAs/SM, ETILE=64, LDSM) ----------
#define SB_W2H   0                 // 34816 B
#define SB_W2L   34816             // 34816 B
#define SB_UH    69632             // 64x136 bf16 = 17408 B
#define SB_UL    87040             // 17408 B
#define SB_W1E   104448            // 2048 f32 = 8192 B
#define SB_W1R   112640            // 512 B
#define SB_BE2   113152            // 512 B
#define EDGE_SMEM_BYTES 113664

__global__ __launch_bounds__(512, 2) void k_edge(const float* __restrict__ x,
                                                 const float* __restrict__ ea,
                                                 const float* __restrict__ We1,
                                                 const float* __restrict__ We2,
                                                 const float* __restrict__ be2) {
    extern __shared__ char smem[];
    __nv_bfloat16* w2h = reinterpret_cast<__nv_bfloat16*>(smem + SB_W2H);
    __nv_bfloat16* w2l = reinterpret_cast<__nv_bfloat16*>(smem + SB_W2L);
    __nv_bfloat16* uhi = reinterpret_cast<__nv_bfloat16*>(smem + SB_UH);
    __nv_bfloat16* ulo = reinterpret_cast<__nv_bfloat16*>(smem + SB_UL);
    float* W1e_s = reinterpret_cast<float*>(smem + SB_W1E);
    float* W1r_s = reinterpret_cast<float*>(smem + SB_W1R);
    float* be2_s = reinterpret_cast<float*>(smem + SB_BE2);

    const int t = threadIdx.x;
    const int w = t >> 5, lane = t & 31;

    // stage loop-invariant weights once per block
    for (int i = t; i < 16384; i += 512) {
        const int k = i >> 7, c = i & 127;
        const float v = We2[i];
        const __nv_bfloat16 hi = __float2bfloat16(v);
        w2h[c * BSTRIDE + k] = hi;
        w2l[c * BSTRIDE + k] = __float2bfloat16(v - __bfloat162float(hi));
    }
    for (int i = t; i < 2048; i += 512) W1e_s[i] = We1[257 * 128 + i];
    if (t < 128) {
        W1r_s[t] = We1[256 * 128 + t];
        be2_s[t] = be2[t];
    }
    __syncthreads();

    const float4 wr = *reinterpret_cast<const float4*>(W1r_s + lane * 4);

    // Phase-B tiling: 16 warps -> m16 (mt2 = w&3) x n32 (nq2 = w>>2)
    const int mt2 = w & 3;
    const int nq2 = w >> 2;
    const int g   = lane >> 2;
    const int tq  = lane & 3;

    // ldmatrix lane maps
    const int rA = lane & 15;
    const int kA = (lane & 16) ? 8 : 0;
    const int rB = ((lane >> 4) & 1) * 8 + (lane & 7);
    const int kB = (lane & 8) ? 8 : 0;
    const uint32_t uhi_s = (uint32_t)__cvta_generic_to_shared(uhi);
    const uint32_t ulo_s = (uint32_t)__cvta_generic_to_shared(ulo);
    const uint32_t w2h_s = (uint32_t)__cvta_generic_to_shared(w2h);
    const uint32_t w2l_s = (uint32_t)__cvta_generic_to_shared(w2l);
    const uint32_t aoff  = (uint32_t)(((mt2 * 16 + rA) * BSTRIDE + kA) * 2);
    const uint32_t boff  = (uint32_t)(((nq2 * 32 + rB) * BSTRIDE + kB) * 2);
    const uint32_t mstep = 16 * BSTRIDE * 2;

    for (int tile = blockIdx.x; tile < NUM_ETILES; tile += EGRID) {
        const int e0 = tile * ETILE;
        __syncthreads();   // protect u buffers vs previous tile readers

        // ---- Phase A: 16 warps x 4 edges; u split hi/lo -> smem
        {
            const int ebase = w * 4;
            const int co    = lane * 4;
            int r4 = 0, c4 = 0;
            float rad4 = 0.f;
            if (lane < 4) {
                const int eg = e0 + ebase + lane;
                r4 = g_row[eg];
                c4 = g_col[eg];
                const float dx = x[r4 * 3 + 0] - x[c4 * 3 + 0];
                const float dy = x[r4 * 3 + 1] - x[c4 * 3 + 1];
                const float dz = x[r4 * 3 + 2] - x[c4 * 3 + 2];
                rad4 = dx * dx + dy * dy + dz * dz;
            }
            float acc[4][4];
#pragma unroll
            for (int ii = 0; ii < 4; ii++) {
                const int r   = __shfl_sync(0xffffffffu, r4, ii);
                const int c   = __shfl_sync(0xffffffffu, c4, ii);
                const float rad = __shfl_sync(0xffffffffu, rad4, ii);
                const float4 a4 = *reinterpret_cast<const float4*>(g_hAB + (size_t)r * 256 + co);
                const float4 b4 = *reinterpret_cast<const float4*>(g_hAB + (size_t)c * 256 + 128 + co);
                acc[ii][0] = fmaf(rad, wr.x, a4.x + b4.x);
                acc[ii][1] = fmaf(rad, wr.y, a4.y + b4.y);
                acc[ii][2] = fmaf(rad, wr.z, a4.z + b4.z);
                acc[ii][3] = fmaf(rad, wr.w, a4.w + b4.w);
            }
#pragma unroll
            for (int jb = 0; jb < 4; jb++) {
                float4 wv[4];
#pragma unroll
                for (int q = 0; q < 4; q++)
                    wv[q] = *reinterpret_cast<const float4*>(W1e_s + (jb * 4 + q) * 128 + co);
#pragma unroll
                for (int ii = 0; ii < 4; ii++) {
                    const float4 e4 = __ldg(reinterpret_cast<const float4*>(
                        ea + (size_t)(e0 + ebase + ii) * 16 + jb * 4));
                    const float ev[4] = {e4.x, e4.y, e4.z, e4.w};
#pragma unroll
                    for (int q = 0; q < 4; q++) {
                        acc[ii][0] = fmaf(ev[q], wv[q].x, acc[ii][0]);
                        acc[ii][1] = fmaf(ev[q], wv[q].y, acc[ii][1]);
                        acc[ii][2] = fmaf(ev[q], wv[q].z, acc[ii][2]);
                        acc[ii][3] = fmaf(ev[q], wv[q].w, acc[ii][3]);
                    }
                }
            }
#pragma unroll
            for (int ii = 0; ii < 4; ii++) {
                const int e = ebase + ii;
                const float sx = silu_f(acc[ii][0]), sy = silu_f(acc[ii][1]);
                const float sz = silu_f(acc[ii][2]), sw = silu_f(acc[ii][3]);
                float la, lb, lc, ld;
                const uint2 hv = pack_hi4(sx, sy, sz, sw, la, lb, lc, ld);
                *reinterpret_cast<uint2*>(uhi + e * BSTRIDE + co) = hv;
                *reinterpret_cast<uint2*>(ulo + e * BSTRIDE + co) = pack_bf4(la, lb, lc, ld);
            }
        }
        __syncthreads();

        // ---- Phase B: D = u_hi@W_hi + u_lo@W_hi + u_hi@W_lo (LDSM + mma)
        {
            float d[4][4];
#pragma unroll
            for (int nt = 0; nt < 4; nt++)
#pragma unroll
                for (int j = 0; j < 4; j++) d[nt][j] = 0.f;

#pragma unroll
            for (int ks = 0; ks < 8; ks++) {
                const uint32_t kb2 = ks * 32;
                uint32_t ah[4], al[4], bh[2][4], bl[2][4];
                ldsm4(ah, uhi_s + aoff + kb2);
                ldsm4(al, ulo_s + aoff + kb2);
                ldsm4(bh[0], w2h_s + boff + kb2);
                ldsm4(bh[1], w2h_s + boff + mstep + kb2);
                ldsm4(bl[0], w2l_s + boff + kb2);
                ldsm4(bl[1], w2l_s + boff + mstep + kb2);
#pragma unroll
                for (int p = 0; p < 2; p++)
#pragma unroll
                    for (int sub = 0; sub < 2; sub++) {
                        const int nt = p * 2 + sub;
                        const uint32_t b0 = bh[p][sub * 2], b1 = bh[p][sub * 2 + 1];
                        mma_bf16(d[nt], ah[0], ah[1], ah[2], ah[3], b0, b1);
                        mma_bf16(d[nt], al[0], al[1], al[2], al[3], b0, b1);
                    }
#pragma unroll
                for (int p = 0; p < 2; p++)
#pragma unroll
                    for (int sub = 0; sub < 2; sub++) {
                        const int nt = p * 2 + sub;
                        const uint32_t b0 = bl[p][sub * 2], b1 = bl[p][sub * 2 + 1];
                        mma_bf16(d[nt], ah[0], ah[1], ah[2], ah[3], b0, b1);
                    }
            }

            // epilogue: silu(+bias), shfl-pair, red.v4 scatter
            const int er0 = g_row[e0 + mt2 * 16 + g];
            const int er1 = g_row[e0 + mt2 * 16 + g + 8];
            const bool evenq = (tq & 1) == 0;
#pragma unroll
            for (int nt = 0; nt < 4; nt++) {
                const int col = nq2 * 32 + nt * 8 + 2 * tq;
                const float b0v = be2_s[col];
                const float b1v = be2_s[col + 1];
                const float v00 = silu_f(d[nt][0] + b0v);
                const float v01 = silu_f(d[nt][1] + b1v);
                const float v10 = silu_f(d[nt][2] + b0v);
                const float v11 = silu_f(d[nt][3] + b1v);
                const float p00 = __shfl_xor_sync(0xffffffffu, v00, 1);
                const float p01 = __shfl_xor_sync(0xffffffffu, v01, 1);
                const float p10 = __shfl_xor_sync(0xffffffffu, v10, 1);
                const float p11 = __shfl_xor_sync(0xffffffffu, v11, 1);
                const int colbase = nq2 * 32 + nt * 8 + (tq & 2) * 2;
                if (evenq) {
                    asm volatile("red.global.add.v4.f32 [%0], {%1, %2, %3, %4};"
                                 :: "l"(g_agg + (size_t)er0 * 128 + colbase),
                                    "f"(v00), "f"(v01), "f"(p00), "f"(p01) : "memory");
                } else {
                    asm volatile("red.global.add.v4.f32 [%0], {%1, %2, %3, %4};"
                                 :: "l"(g_agg + (size_t)er1 * 128 + colbase),
                                    "f"(p10), "f"(p11), "f"(v10), "f"(v11) : "memory");
                }
            }
        }
    }
}

// ---------------- k_node (launch #5): mid = silu(hn1 + agg@Wn1b); scatter to pools ----
#define NODE_SMEM_FLOATS (128 * 36 + 32)
#define NODE_SMEM_BYTES  (NODE_SMEM_FLOATS * 4)

__global__ __launch_bounds__(256) void k_node(const float* __restrict__ h,
                                              const float* __restrict__ Wn1) {
    extern __shared__ float sm[];
    float* a_s = sm;
    int*   b_s = reinterpret_cast<int*>(sm + 128 * 36);

    const int n0 = blockIdx.x * NTILE;
    const int t = threadIdx.x;
    {
        const int n  = t >> 3;
        const int k4 = t & 7;
        const int ng = n0 + n;
#pragma unroll
        for (int j = 0; j < 4; j++) {
            const int k = k4 * 16 + j * 4;
            float4 w = make_float4(0.f, 0.f, 0.f, 0.f);
            if (ng < N_NODES)
                w = *reinterpret_cast<const float4*>(g_agg + (size_t)ng * 128 + k);
            a_s[(k + 0) * 36 + n] = w.x;
            a_s[(k + 1) * 36 + n] = w.y;
            a_s[(k + 2) * 36 + n] = w.z;
            a_s[(k + 3) * 36 + n] = w.w;
        }
        if (t < 32) b_s[t] = (n0 + t < N_NODES) ? g_batch[n0 + t] : 0;
    }
    __syncthreads();

    const int cg = t & 31;
    const int ng = t >> 5;
    const int cn = cg * 4;
    float acc[4][4];
#pragma unroll
    for (int i = 0; i < 4; i++)
#pragma unroll
        for (int j = 0; j < 4; j++) acc[i][j] = 0.f;

    for (int k = 0; k < 128; k++) {
        float av[4];
#pragma unroll
        for (int i = 0; i < 4; i++) av[i] = a_s[k * 36 + ng * 4 + i];
        const float4 w = __ldg(reinterpret_cast<const float4*>(Wn1 + (128 + k) * 128 + cn));
        const float wv[4] = {w.x, w.y, w.z, w.w};
#pragma unroll
        for (int i = 0; i < 4; i++)
#pragma unroll
            for (int j = 0; j < 4; j++) acc[i][j] = fmaf(av[i], wv[j], acc[i][j]);
    }
#pragma unroll
    for (int i = 0; i < 4; i++) {
        const int n = n0 + ng * 4 + i;
        if (n < N_NODES) {
            const int b = b_s[ng * 4 + i];
            const float4 hn = *reinterpret_cast<const float4*>(g_hn1 + (size_t)n * 128 + cn);
            const float m0 = silu_f(acc[i][0] + hn.x);
            const float m1 = silu_f(acc[i][1] + hn.y);
            const float m2 = silu_f(acc[i][2] + hn.z);
            const float m3 = silu_f(acc[i][3] + hn.w);
            asm volatile("red.global.add.v4.f32 [%0], {%1, %2, %3, %4};"
                         :: "l"(g_poolm + b * 128 + cn), "f"(m0), "f"(m1), "f"(m2), "f"(m3)
                         : "memory");
            const float4 hv = *reinterpret_cast<const float4*>(h + (size_t)n * 128 + cn);
            asm volatile("red.global.add.v4.f32 [%0], {%1, %2, %3, %4};"
                         :: "l"(g_pool + b * 128 + cn), "f"(hv.x), "f"(hv.y), "f"(hv.z), "f"(hv.w)
                         : "memory");
        }
    }
    if (t < 32 && n0 + t < N_NODES) atomicAdd(&g_cnt[b_s[t]], 1.0f);
}

// ---------------- k_pool_final (launch #6) ----------------
__global__ void k_pool_final(const float* __restrict__ Wn2,
                             const float* __restrict__ bn2,
                             float* __restrict__ out) {
    __shared__ float pm[128];
    const int g = blockIdx.x;
    const int c = threadIdx.x;
    pm[c] = g_poolm[g * 128 + c];
    __syncthreads();
    float dot = 0.f;
    for (int k = 0; k < 128; k++)
        dot = fmaf(pm[k], __ldg(Wn2 + k * 128 + c), dot);
    const float cnt = g_cnt[g];
    const float s = g_pool[g * 128 + c] + dot + cnt * __ldg(bn2 + c);
    out[g * 128 + c] = s / fmaxf(cnt, 1.0f);
}

// ---------------- launcher ----------------
extern "C" void kernel_launch(void* const* d_in, const int* in_sizes, int n_in,
                              void* d_out, int out_size) {
    const float* h   = (const float*)d_in[0];
    const void*  ei  = d_in[1];
    const float* x   = (const float*)d_in[2];
    const float* ea  = (const float*)d_in[3];
    const void*  bat = d_in[4];
    const float* We1 = (const float*)d_in[5];
    const float* be1 = (const float*)d_in[6];
    const float* We2 = (const float*)d_in[7];
    const float* be2 = (const float*)d_in[8];
    const float* Wn1 = (const float*)d_in[9];
    const float* bn1 = (const float*)d_in[10];
    const float* Wn2 = (const float*)d_in[11];
    const float* bn2 = (const float*)d_in[12];
    float* out = (float*)d_out;

    cudaFuncSetAttribute(k_pre,  cudaFuncAttributeMaxDynamicSharedMemorySize, PRE_SMEM_BYTES);
    cudaFuncSetAttribute(k_edge, cudaFuncAttributeMaxDynamicSharedMemorySize, EDGE_SMEM_BYTES);
    cudaFuncSetAttribute(k_node, cudaFuncAttributeMaxDynamicSharedMemorySize, NODE_SMEM_BYTES);

    k_init<<<(N_NODES * HID / 4 + 255) / 256, 256>>>(ei);                       // #1
    k_cvt_idx<<<(N_EDGES + 255) / 256, 256>>>(ei, bat);                         // #2
    k_pre<<<PGRID, 512, PRE_SMEM_BYTES>>>(h, We1, be1, Wn1, bn1);               // #3
    k_edge<<<EGRID, 512, EDGE_SMEM_BYTES>>>(x, ea, We1, We2, be2);              // #4 (ncu slot)
    k_node<<<(N_NODES + NTILE - 1) / NTILE, 256, NODE_SMEM_BYTES>>>(h, Wn1);    // #5
    k_pool_final<<<N_GRAPHS, HID>>>(Wn2, bn2, out);                             // #6
}